// round 1
// baseline (speedup 1.0000x reference)
#include <cuda_runtime.h>
#include <cuda_fp16.h>
#include <mma.h>

using namespace nvcuda;

// Problem constants
#define BB   128
#define NN   197
#define HH   12
#define DH   64
#define DIM  768
#define MTOT (BB * NN)          // 25216 (divisible by 128)
#define TABLE 730

// ---------------- scratch (device globals; no allocations allowed) ----------
__device__ alignas(16) __half g_Xh[(size_t)MTOT * DIM];      // x in fp16
__device__ alignas(16) __half g_Wqkv[(size_t)3 * DIM * DIM]; // qkv_w fp16
__device__ alignas(16) __half g_Wp[(size_t)DIM * DIM];       // proj_w fp16
__device__ alignas(16) __half g_Q[(size_t)BB * HH * NN * DH]; // scaled q
__device__ alignas(16) __half g_K[(size_t)BB * HH * NN * DH];
__device__ alignas(16) __half g_V[(size_t)BB * HH * NN * DH];
__device__ alignas(16) __half g_AO[(size_t)MTOT * DIM];       // attn out [B,N,H*DH]
__device__ alignas(16) float  g_bias[(size_t)HH * NN * NN];   // expanded bias

// ---------------- fp32 -> fp16 convert ----------------
__global__ void f2h_kernel(const float* __restrict__ src, int n2, int which) {
    __half* dst = (which == 0) ? g_Xh : (which == 1) ? g_Wqkv : g_Wp;
    int i = blockIdx.x * blockDim.x + threadIdx.x;
    if (i < n2) {
        float2 v = reinterpret_cast<const float2*>(src)[i];
        reinterpret_cast<__half2*>(dst)[i] = __floats2half2_rn(v.x, v.y);
    }
}

// ---------------- expand relative-position bias: [H,197,197] -----------------
__global__ void bias_kernel(const float* __restrict__ tab, const int* __restrict__ ridx) {
    int idx = blockIdx.x * blockDim.x + threadIdx.x;
    const int TOT = HH * NN * NN;
    if (idx >= TOT) return;
    int h = idx / (NN * NN);
    int rem = idx - h * (NN * NN);
    g_bias[idx] = tab[ridx[rem] * HH + h];
}

// ---------------- WMMA GEMM: C[M, Ncols] = A[M,768] * W[Ncols,768]^T --------
// mode 0: A=g_Xh, W=g_Wqkv (Ncols=2304), scatter epilogue into Q(scaled)/K/V
// mode 1: A=g_AO, W=g_Wp   (Ncols=768),  epilogue adds bias, writes fp32 out
__global__ void gemm_kernel(int mode, const float* __restrict__ bias,
                            float* __restrict__ outf) {
    __shared__ alignas(16) char smraw[36864];
    __half (*As)[40] = reinterpret_cast<__half(*)[40]>(smraw);             // 128x32 (+pad)
    __half (*Bs)[40] = reinterpret_cast<__half(*)[40]>(smraw + 128 * 40 * 2); // 64x32
    float  (*Cs)[72] = reinterpret_cast<float(*)[72]>(smraw);              // epilogue reuse

    const __half* A = (mode == 0) ? g_Xh : g_AO;
    const __half* W = (mode == 0) ? g_Wqkv : g_Wp;

    const int m0 = blockIdx.y * 128;
    const int n0 = blockIdx.x * 64;
    const int tid = threadIdx.x;
    const int wid = tid >> 5;
    const int wm = wid >> 1, wn = wid & 1;   // 4 x 2 warp grid, each warp 32x32

    wmma::fragment<wmma::accumulator, 16, 16, 16, float> acc[2][2];
#pragma unroll
    for (int i = 0; i < 2; i++)
#pragma unroll
        for (int j = 0; j < 2; j++) wmma::fill_fragment(acc[i][j], 0.0f);

    for (int kt = 0; kt < DIM; kt += 32) {
        // A tile 128x32: 512 uint4
#pragma unroll
        for (int it = 0; it < 2; it++) {
            int idx = tid + it * 256;
            int r = idx >> 2, c8 = idx & 3;
            *reinterpret_cast<uint4*>(&As[r][c8 * 8]) =
                *reinterpret_cast<const uint4*>(&A[(size_t)(m0 + r) * DIM + kt + c8 * 8]);
        }
        // B tile 64x32: 256 uint4
        {
            int r = tid >> 2, c8 = tid & 3;
            *reinterpret_cast<uint4*>(&Bs[r][c8 * 8]) =
                *reinterpret_cast<const uint4*>(&W[(size_t)(n0 + r) * DIM + kt + c8 * 8]);
        }
        __syncthreads();
#pragma unroll
        for (int kk = 0; kk < 32; kk += 16) {
            wmma::fragment<wmma::matrix_a, 16, 16, 16, __half, wmma::row_major> af[2];
            wmma::fragment<wmma::matrix_b, 16, 16, 16, __half, wmma::col_major> bf[2];
#pragma unroll
            for (int i = 0; i < 2; i++)
                wmma::load_matrix_sync(af[i], &As[wm * 32 + i * 16][kk], 40);
#pragma unroll
            for (int j = 0; j < 2; j++)
                wmma::load_matrix_sync(bf[j], &Bs[wn * 32 + j * 16][kk], 40);
#pragma unroll
            for (int i = 0; i < 2; i++)
#pragma unroll
                for (int j = 0; j < 2; j++)
                    wmma::mma_sync(acc[i][j], af[i], bf[j], acc[i][j]);
        }
        __syncthreads();
    }

    // stage accumulators in smem
#pragma unroll
    for (int i = 0; i < 2; i++)
#pragma unroll
        for (int j = 0; j < 2; j++)
            wmma::store_matrix_sync(&Cs[wm * 32 + i * 16][wn * 32 + j * 16],
                                    acc[i][j], 72, wmma::mem_row_major);
    __syncthreads();

    if (mode == 1) {
        for (int idx = tid; idx < 128 * 64; idx += 256) {
            int r = idx >> 6, c = idx & 63;
            int m = m0 + r, n = n0 + c;
            outf[(size_t)m * DIM + n] = Cs[r][c] + bias[n];
        }
    } else {
        for (int idx = tid; idx < 128 * 64; idx += 256) {
            int r = idx >> 6, c = idx & 63;
            int m = m0 + r, n = n0 + c;
            float v = Cs[r][c];
            int which = n / DIM;
            int rem = n - which * DIM;
            int h = rem >> 6, d = rem & 63;
            int b = m / NN, t = m - b * NN;
            size_t off = ((size_t)(b * HH + h) * NN + t) * DH + d;
            if (which == 0)      g_Q[off] = __float2half(v * 0.125f);  // * DH^-0.5
            else if (which == 1) g_K[off] = __float2half(v);
            else                 g_V[off] = __float2half(v);
        }
    }
}

// ---------------- fused attention: one CTA per (b, h) ------------------------
// smem: K[208][72]h, V[208][72]h, Q[64][72]h, S[64][216]f, P[64][216]h, rinv[64]f
#define SM_K   0
#define SM_V   29952
#define SM_Q   59904
#define SM_S   69120
#define SM_P   124416
#define SM_R   152064
#define SMEM_ATTN 152320

__global__ void attn_kernel() {
    extern __shared__ __align__(16) char sm[];
    __half* Ksm = reinterpret_cast<__half*>(sm + SM_K);
    __half* Vsm = reinterpret_cast<__half*>(sm + SM_V);
    __half* Qsm = reinterpret_cast<__half*>(sm + SM_Q);
    float*  Ssm = reinterpret_cast<float*>(sm + SM_S);
    __half* Psm = reinterpret_cast<__half*>(sm + SM_P);
    float*  Rinv = reinterpret_cast<float*>(sm + SM_R);

    const int bh = blockIdx.x;
    const int b = bh / HH, h = bh - b * HH;
    const __half* Kg = g_K + (size_t)bh * NN * DH;
    const __half* Vg = g_V + (size_t)bh * NN * DH;
    const __half* Qg = g_Q + (size_t)bh * NN * DH;
    const int tid = threadIdx.x, lane = tid & 31, wid = tid >> 5;

    // Load K, V (zero-pad rows 197..207)
    for (int idx = tid; idx < 208 * 8; idx += 256) {
        int r = idx >> 3, c = idx & 7;
        uint4 z = make_uint4(0, 0, 0, 0);
        uint4 kv = (r < NN) ? *reinterpret_cast<const uint4*>(&Kg[r * DH + c * 8]) : z;
        uint4 vv = (r < NN) ? *reinterpret_cast<const uint4*>(&Vg[r * DH + c * 8]) : z;
        *reinterpret_cast<uint4*>(&Ksm[r * 72 + c * 8]) = kv;
        *reinterpret_cast<uint4*>(&Vsm[r * 72 + c * 8]) = vv;
    }

    for (int m0 = 0; m0 < NN; m0 += 64) {
        const int valid = min(64, NN - m0);
        // load Q chunk (zero-pad)
        for (int idx = tid; idx < 64 * 8; idx += 256) {
            int r = idx >> 3, c = idx & 7;
            uint4 q = (r < valid)
                ? *reinterpret_cast<const uint4*>(&Qg[(m0 + r) * DH + c * 8])
                : make_uint4(0, 0, 0, 0);
            *reinterpret_cast<uint4*>(&Qsm[r * 72 + c * 8]) = q;
        }
        __syncthreads();

        // S = Q K^T  (4 x 13 tiles of 16x16)
        for (int t = wid; t < 52; t += 8) {
            int rt = t & 3, ct = t >> 2;
            wmma::fragment<wmma::accumulator, 16, 16, 16, float> c;
            wmma::fill_fragment(c, 0.0f);
#pragma unroll
            for (int kk = 0; kk < 64; kk += 16) {
                wmma::fragment<wmma::matrix_a, 16, 16, 16, __half, wmma::row_major> a;
                wmma::fragment<wmma::matrix_b, 16, 16, 16, __half, wmma::col_major> bb;
                wmma::load_matrix_sync(a, Qsm + rt * 16 * 72 + kk, 72);
                wmma::load_matrix_sync(bb, Ksm + ct * 16 * 72 + kk, 72);
                wmma::mma_sync(c, a, bb, c);
            }
            wmma::store_matrix_sync(Ssm + rt * 16 * 216 + ct * 16, c, 216,
                                    wmma::mem_row_major);
        }
        __syncthreads();

        // softmax: warp handles 8 rows; bias added here; P holds un-normalized exp
        {
            int r0 = wid * 8;
#pragma unroll
            for (int rr = 0; rr < 8; rr++) {
                int r = r0 + rr;
                int qr = min(m0 + r, NN - 1);
                const float* brow = g_bias + ((size_t)h * NN + qr) * NN;
                float mx = -1e30f;
                for (int c = lane; c < NN; c += 32) {
                    float v = Ssm[r * 216 + c] + brow[c];
                    Ssm[r * 216 + c] = v;
                    mx = fmaxf(mx, v);
                }
#pragma unroll
                for (int o = 16; o; o >>= 1) mx = fmaxf(mx, __shfl_xor_sync(~0u, mx, o));
                float s = 0.0f;
                for (int c = lane; c < NN; c += 32) {
                    float e = __expf(Ssm[r * 216 + c] - mx);
                    s += e;
                    Psm[r * 216 + c] = __float2half(e);
                }
#pragma unroll
                for (int o = 16; o; o >>= 1) s += __shfl_xor_sync(~0u, s, o);
                if (lane == 0) Rinv[r] = 1.0f / s;
                if (lane < 11) Psm[r * 216 + NN + lane] = __float2half(0.0f);
            }
        }
        __syncthreads();

        // O = P V  (4 x 4 tiles), accumulate fp32, store into Ssm as [64][72]
        for (int t = wid; t < 16; t += 8) {
            int rt = t & 3, ct = t >> 2;
            wmma::fragment<wmma::accumulator, 16, 16, 16, float> c;
            wmma::fill_fragment(c, 0.0f);
#pragma unroll
            for (int kk = 0; kk < 13; kk++) {
                wmma::fragment<wmma::matrix_a, 16, 16, 16, __half, wmma::row_major> a;
                wmma::fragment<wmma::matrix_b, 16, 16, 16, __half, wmma::row_major> bb;
                wmma::load_matrix_sync(a, Psm + rt * 16 * 216 + kk * 16, 216);
                wmma::load_matrix_sync(bb, Vsm + kk * 16 * 72 + ct * 16, 72);
                wmma::mma_sync(c, a, bb, c);
            }
            wmma::store_matrix_sync(Ssm + rt * 16 * 72 + ct * 16, c, 72,
                                    wmma::mem_row_major);
        }
        __syncthreads();

        // write out with per-row normalization
        for (int idx = tid; idx < 64 * 64; idx += 256) {
            int r = idx >> 6, d = idx & 63;
            if (r < valid) {
                float v = Ssm[r * 72 + d] * Rinv[r];
                g_AO[((size_t)(b * NN + m0 + r) * HH + h) * DH + d] = __float2half(v);
            }
        }
        __syncthreads();
    }
}

// ---------------- launch ----------------
extern "C" void kernel_launch(void* const* d_in, const int* in_sizes, int n_in,
                              void* d_out, int out_size) {
    const float* x     = (const float*)d_in[0];
    const float* qkvw  = (const float*)d_in[1];
    const float* projw = (const float*)d_in[2];
    const float* projb = (const float*)d_in[3];
    const float* btab  = (const float*)d_in[4];
    const int*   ridx  = (const int*)d_in[5];
    float* out = (float*)d_out;

    cudaFuncSetAttribute(attn_kernel, cudaFuncAttributeMaxDynamicSharedMemorySize,
                         SMEM_ATTN);

    const int nx = MTOT * DIM;          // 19,365,888
    const int nw1 = 3 * DIM * DIM;      // 1,769,472
    const int nw2 = DIM * DIM;          // 589,824
    f2h_kernel<<<(nx / 2 + 255) / 256, 256>>>(x, nx / 2, 0);
    f2h_kernel<<<(nw1 / 2 + 255) / 256, 256>>>(qkvw, nw1 / 2, 1);
    f2h_kernel<<<(nw2 / 2 + 255) / 256, 256>>>(projw, nw2 / 2, 2);

    const int nb = HH * NN * NN;
    bias_kernel<<<(nb + 255) / 256, 256>>>(btab, ridx);

    // QKV: M=25216, N=2304
    gemm_kernel<<<dim3(3 * DIM / 64, MTOT / 128), 256>>>(0, nullptr, nullptr);

    // fused attention
    attn_kernel<<<BB * HH, 256, SMEM_ATTN>>>();

    // proj: M=25216, N=768
    gemm_kernel<<<dim3(DIM / 64, MTOT / 128), 256>>>(1, projb, out);
}

// round 2
// speedup vs baseline: 1.0375x; 1.0375x over previous
#include <cuda_runtime.h>
#include <cuda_fp16.h>
#include <mma.h>

using namespace nvcuda;

// Problem constants
#define BB   128
#define NN   197
#define HH   12
#define DH   64
#define DIM  768
#define MTOT (BB * NN)          // 25216 (divisible by 128)
#define TABLE 730

// ---------------- scratch (device globals; no allocations allowed) ----------
__device__ alignas(16) __half g_Xh[(size_t)MTOT * DIM];      // x in fp16
__device__ alignas(16) __half g_Wqkv[(size_t)3 * DIM * DIM]; // qkv_w fp16
__device__ alignas(16) __half g_Wp[(size_t)DIM * DIM];       // proj_w fp16
__device__ alignas(16) __half g_Q[(size_t)BB * HH * NN * DH]; // scaled q
__device__ alignas(16) __half g_K[(size_t)BB * HH * NN * DH];
__device__ alignas(16) __half g_V[(size_t)BB * HH * NN * DH];
__device__ alignas(16) __half g_AO[(size_t)MTOT * DIM];       // attn out [B,N,H*DH]
__device__ alignas(16) float  g_bias[(size_t)HH * NN * NN];   // expanded bias

// ---------------- cp.async helpers ----------------
__device__ __forceinline__ void cpa16(void* dst, const void* src) {
    unsigned sa = (unsigned)__cvta_generic_to_shared(dst);
    asm volatile("cp.async.cg.shared.global [%0], [%1], 16;" :: "r"(sa), "l"(src));
}
#define CP_COMMIT() asm volatile("cp.async.commit_group;")
#define CP_WAIT(n)  asm volatile("cp.async.wait_group %0;" :: "n"(n))

// ---------------- fp32 -> fp16 convert ----------------
__global__ void f2h_kernel(const float* __restrict__ src, int n2, int which) {
    __half* dst = (which == 0) ? g_Xh : (which == 1) ? g_Wqkv : g_Wp;
    int i = blockIdx.x * blockDim.x + threadIdx.x;
    if (i < n2) {
        float2 v = reinterpret_cast<const float2*>(src)[i];
        reinterpret_cast<__half2*>(dst)[i] = __floats2half2_rn(v.x, v.y);
    }
}

// ---------------- expand relative-position bias: [H,197,197] -----------------
__global__ void bias_kernel(const float* __restrict__ tab, const int* __restrict__ ridx) {
    int idx = blockIdx.x * blockDim.x + threadIdx.x;
    const int TOT = HH * NN * NN;
    if (idx >= TOT) return;
    int h = idx / (NN * NN);
    int rem = idx - h * (NN * NN);
    g_bias[idx] = tab[ridx[rem] * HH + h];
}

// ---------------- WMMA GEMM: C[M, Ncols] = A[M,768] * W[Ncols,768]^T --------
// 128x128 block tile, cp.async double-buffered, 8 warps x (64x32 out).
// mode 0: A=g_Xh, W=g_Wqkv (Ncols=2304), scatter epilogue into Q(scaled)/K/V
// mode 1: A=g_AO, W=g_Wp   (Ncols=768),  epilogue adds bias, writes fp32 out
#define GBK 32
#define GNT (DIM / GBK)   // 24 k-steps

__global__ __launch_bounds__(256, 2)
void gemm_kernel(int mode, const float* __restrict__ bias, float* __restrict__ outf) {
    __shared__ alignas(16) char smraw[40960];
    // stage layout (bytes): As0 @0, Bs0 @10240, As1 @20480, Bs1 @30720
    __half* AsP[2] = { reinterpret_cast<__half*>(smraw),
                       reinterpret_cast<__half*>(smraw + 20480) };
    __half* BsP[2] = { reinterpret_cast<__half*>(smraw + 10240),
                       reinterpret_cast<__half*>(smraw + 30720) };
    float (*Cs)[72] = reinterpret_cast<float(*)[72]>(smraw);  // epilogue overlay

    const __half* A = (mode == 0) ? g_Xh : g_AO;
    const __half* W = (mode == 0) ? g_Wqkv : g_Wp;

    const int m0 = blockIdx.y * 128;
    const int n0 = blockIdx.x * 128;
    const int tid = threadIdx.x;
    const int wid = tid >> 5;
    const int wm = wid >> 2, wn = wid & 3;   // 2 x 4 warp grid; warp owns 64x32

    wmma::fragment<wmma::accumulator, 16, 16, 16, float> acc[4][2];
#pragma unroll
    for (int i = 0; i < 4; i++)
#pragma unroll
        for (int j = 0; j < 2; j++) wmma::fill_fragment(acc[i][j], 0.0f);

    // prefetch lambda: stage s <- k-step kt
    auto prefetch = [&](int kt, int s) {
        const __half* Ab = A + (size_t)m0 * DIM + kt * GBK;
        const __half* Bb = W + (size_t)n0 * DIM + kt * GBK;
#pragma unroll
        for (int t = tid; t < 512; t += 256) {
            int r = t >> 2, c = t & 3;
            cpa16(AsP[s] + r * 40 + c * 8, Ab + (size_t)r * DIM + c * 8);
        }
#pragma unroll
        for (int t = tid; t < 512; t += 256) {
            int r = t >> 2, c = t & 3;
            cpa16(BsP[s] + r * 40 + c * 8, Bb + (size_t)r * DIM + c * 8);
        }
    };

    prefetch(0, 0);
    CP_COMMIT();

    for (int kt = 0; kt < GNT; kt++) {
        const int s = kt & 1;
        if (kt + 1 < GNT) {
            prefetch(kt + 1, 1 - s);
            CP_COMMIT();
            CP_WAIT(1);
        } else {
            CP_WAIT(0);
        }
        __syncthreads();
#pragma unroll
        for (int kk = 0; kk < GBK; kk += 16) {
            wmma::fragment<wmma::matrix_a, 16, 16, 16, __half, wmma::row_major> af[4];
            wmma::fragment<wmma::matrix_b, 16, 16, 16, __half, wmma::col_major> bf[2];
#pragma unroll
            for (int i = 0; i < 4; i++)
                wmma::load_matrix_sync(af[i], AsP[s] + (wm * 64 + i * 16) * 40 + kk, 40);
#pragma unroll
            for (int j = 0; j < 2; j++)
                wmma::load_matrix_sync(bf[j], BsP[s] + (wn * 32 + j * 16) * 40 + kk, 40);
#pragma unroll
            for (int i = 0; i < 4; i++)
#pragma unroll
                for (int j = 0; j < 2; j++)
                    wmma::mma_sync(acc[i][j], af[i], bf[j], acc[i][j]);
        }
        __syncthreads();
    }

    // Epilogue: two 64-col passes through smem (Cs overlays the stage buffers)
#pragma unroll
    for (int half = 0; half < 2; half++) {
        if ((wn >> 1) == half) {
#pragma unroll
            for (int i = 0; i < 4; i++)
#pragma unroll
                for (int j = 0; j < 2; j++)
                    wmma::store_matrix_sync(&Cs[wm * 64 + i * 16][(wn & 1) * 32 + j * 16],
                                            acc[i][j], 72, wmma::mem_row_major);
        }
        __syncthreads();
        if (mode == 1) {
            for (int idx = tid; idx < 128 * 64; idx += 256) {
                int r = idx >> 6, c = idx & 63;
                int m = m0 + r, n = n0 + half * 64 + c;
                outf[(size_t)m * DIM + n] = Cs[r][c] + bias[n];
            }
        } else {
            for (int idx = tid; idx < 128 * 64; idx += 256) {
                int r = idx >> 6, c = idx & 63;
                int m = m0 + r, n = n0 + half * 64 + c;
                float v = Cs[r][c];
                int which = n / DIM;
                int rem = n - which * DIM;
                int h = rem >> 6, d = rem & 63;
                int b = m / NN, t = m - b * NN;
                size_t off = ((size_t)(b * HH + h) * NN + t) * DH + d;
                if (which == 0)      g_Q[off] = __float2half(v * 0.125f);  // * DH^-0.5
                else if (which == 1) g_K[off] = __float2half(v);
                else                 g_V[off] = __float2half(v);
            }
        }
        __syncthreads();
    }
}

// ---------------- fused attention: one CTA per (b, h) ------------------------
// smem: K[208][72]h, V[208][72]h, Q[64][72]h, S[64][216]f, P[64][216]h, rinv[64]f
#define SM_K   0
#define SM_V   29952
#define SM_Q   59904
#define SM_S   69120
#define SM_P   124416
#define SM_R   152064
#define SMEM_ATTN 152320

__global__ void attn_kernel() {
    extern __shared__ __align__(16) char sm[];
    __half* Ksm = reinterpret_cast<__half*>(sm + SM_K);
    __half* Vsm = reinterpret_cast<__half*>(sm + SM_V);
    __half* Qsm = reinterpret_cast<__half*>(sm + SM_Q);
    float*  Ssm = reinterpret_cast<float*>(sm + SM_S);
    __half* Psm = reinterpret_cast<__half*>(sm + SM_P);
    float*  Rinv = reinterpret_cast<float*>(sm + SM_R);

    const int bh = blockIdx.x;
    const int b = bh / HH, h = bh - b * HH;
    const __half* Kg = g_K + (size_t)bh * NN * DH;
    const __half* Vg = g_V + (size_t)bh * NN * DH;
    const __half* Qg = g_Q + (size_t)bh * NN * DH;
    const int tid = threadIdx.x, lane = tid & 31, wid = tid >> 5;

    // Load K, V (zero-pad rows 197..207)
    for (int idx = tid; idx < 208 * 8; idx += 256) {
        int r = idx >> 3, c = idx & 7;
        uint4 z = make_uint4(0, 0, 0, 0);
        uint4 kv = (r < NN) ? *reinterpret_cast<const uint4*>(&Kg[r * DH + c * 8]) : z;
        uint4 vv = (r < NN) ? *reinterpret_cast<const uint4*>(&Vg[r * DH + c * 8]) : z;
        *reinterpret_cast<uint4*>(&Ksm[r * 72 + c * 8]) = kv;
        *reinterpret_cast<uint4*>(&Vsm[r * 72 + c * 8]) = vv;
    }

    for (int m0 = 0; m0 < NN; m0 += 64) {
        const int valid = min(64, NN - m0);
        // load Q chunk (zero-pad)
        for (int idx = tid; idx < 64 * 8; idx += 256) {
            int r = idx >> 3, c = idx & 7;
            uint4 q = (r < valid)
                ? *reinterpret_cast<const uint4*>(&Qg[(m0 + r) * DH + c * 8])
                : make_uint4(0, 0, 0, 0);
            *reinterpret_cast<uint4*>(&Qsm[r * 72 + c * 8]) = q;
        }
        __syncthreads();

        // S = Q K^T  (4 x 13 tiles of 16x16)
        for (int t = wid; t < 52; t += 8) {
            int rt = t & 3, ct = t >> 2;
            wmma::fragment<wmma::accumulator, 16, 16, 16, float> c;
            wmma::fill_fragment(c, 0.0f);
#pragma unroll
            for (int kk = 0; kk < 64; kk += 16) {
                wmma::fragment<wmma::matrix_a, 16, 16, 16, __half, wmma::row_major> a;
                wmma::fragment<wmma::matrix_b, 16, 16, 16, __half, wmma::col_major> bb;
                wmma::load_matrix_sync(a, Qsm + rt * 16 * 72 + kk, 72);
                wmma::load_matrix_sync(bb, Ksm + ct * 16 * 72 + kk, 72);
                wmma::mma_sync(c, a, bb, c);
            }
            wmma::store_matrix_sync(Ssm + rt * 16 * 216 + ct * 16, c, 216,
                                    wmma::mem_row_major);
        }
        __syncthreads();

        // softmax: warp handles 8 rows; bias added here; P holds un-normalized exp
        {
            int r0 = wid * 8;
#pragma unroll
            for (int rr = 0; rr < 8; rr++) {
                int r = r0 + rr;
                int qr = min(m0 + r, NN - 1);
                const float* brow = g_bias + ((size_t)h * NN + qr) * NN;
                float mx = -1e30f;
                for (int c = lane; c < NN; c += 32) {
                    float v = Ssm[r * 216 + c] + brow[c];
                    Ssm[r * 216 + c] = v;
                    mx = fmaxf(mx, v);
                }
#pragma unroll
                for (int o = 16; o; o >>= 1) mx = fmaxf(mx, __shfl_xor_sync(~0u, mx, o));
                float s = 0.0f;
                for (int c = lane; c < NN; c += 32) {
                    float e = __expf(Ssm[r * 216 + c] - mx);
                    s += e;
                    Psm[r * 216 + c] = __float2half(e);
                }
#pragma unroll
                for (int o = 16; o; o >>= 1) s += __shfl_xor_sync(~0u, s, o);
                if (lane == 0) Rinv[r] = 1.0f / s;
                if (lane < 11) Psm[r * 216 + NN + lane] = __float2half(0.0f);
            }
        }
        __syncthreads();

        // O = P V  (4 x 4 tiles), accumulate fp32, store into Ssm as [64][72]
        for (int t = wid; t < 16; t += 8) {
            int rt = t & 3, ct = t >> 2;
            wmma::fragment<wmma::accumulator, 16, 16, 16, float> c;
            wmma::fill_fragment(c, 0.0f);
#pragma unroll
            for (int kk = 0; kk < 13; kk++) {
                wmma::fragment<wmma::matrix_a, 16, 16, 16, __half, wmma::row_major> a;
                wmma::fragment<wmma::matrix_b, 16, 16, 16, __half, wmma::row_major> bb;
                wmma::load_matrix_sync(a, Psm + rt * 16 * 216 + kk * 16, 216);
                wmma::load_matrix_sync(bb, Vsm + kk * 16 * 72 + ct * 16, 72);
                wmma::mma_sync(c, a, bb, c);
            }
            wmma::store_matrix_sync(Ssm + rt * 16 * 72 + ct * 16, c, 72,
                                    wmma::mem_row_major);
        }
        __syncthreads();

        // write out with per-row normalization
        for (int idx = tid; idx < 64 * 64; idx += 256) {
            int r = idx >> 6, d = idx & 63;
            if (r < valid) {
                float v = Ssm[r * 72 + d] * Rinv[r];
                g_AO[((size_t)(b * NN + m0 + r) * HH + h) * DH + d] = __float2half(v);
            }
        }
        __syncthreads();
    }
}

// ---------------- launch ----------------
extern "C" void kernel_launch(void* const* d_in, const int* in_sizes, int n_in,
                              void* d_out, int out_size) {
    const float* x     = (const float*)d_in[0];
    const float* qkvw  = (const float*)d_in[1];
    const float* projw = (const float*)d_in[2];
    const float* projb = (const float*)d_in[3];
    const float* btab  = (const float*)d_in[4];
    const int*   ridx  = (const int*)d_in[5];
    float* out = (float*)d_out;

    cudaFuncSetAttribute(attn_kernel, cudaFuncAttributeMaxDynamicSharedMemorySize,
                         SMEM_ATTN);

    const int nx = MTOT * DIM;          // 19,365,888
    const int nw1 = 3 * DIM * DIM;      // 1,769,472
    const int nw2 = DIM * DIM;          // 589,824

    // launch order chosen so ncu's skip-5 window lands on attn_kernel
    const int nb = HH * NN * NN;
    bias_kernel<<<(nb + 255) / 256, 256>>>(btab, ridx);          // 1
    f2h_kernel<<<(nx / 2 + 255) / 256, 256>>>(x, nx / 2, 0);     // 2
    f2h_kernel<<<(nw1 / 2 + 255) / 256, 256>>>(qkvw, nw1 / 2, 1);// 3
    f2h_kernel<<<(nw2 / 2 + 255) / 256, 256>>>(projw, nw2 / 2, 2);// 4

    // QKV: M=25216, N=2304                                       // 5
    gemm_kernel<<<dim3(3 * DIM / 128, MTOT / 128), 256>>>(0, nullptr, nullptr);

    // fused attention                                            // 6 (profiled)
    attn_kernel<<<BB * HH, 256, SMEM_ATTN>>>();

    // proj: M=25216, N=768                                       // 7
    gemm_kernel<<<dim3(DIM / 128, MTOT / 128), 256>>>(1, projb, out);
}

// round 4
// speedup vs baseline: 1.4975x; 1.4434x over previous
#include <cuda_runtime.h>
#include <cuda_fp16.h>
#include <mma.h>

using namespace nvcuda;

// Problem constants
#define BB   128
#define NN   197
#define HH   12
#define DH   64
#define DIM  768
#define MTOT (BB * NN)          // 25216 (divisible by 128)
#define TABLE 730
#define NP   208                // padded N (cols) for bias / S tiles
#define NPR  256                // padded N (rows) for bias: 4 chunks of 64

// ---------------- scratch (device globals; no allocations allowed) ----------
__device__ alignas(16) __half g_Xh[(size_t)MTOT * DIM];      // x in fp16
__device__ alignas(16) __half g_Wqkv[(size_t)3 * DIM * DIM]; // qkv_w fp16
__device__ alignas(16) __half g_Wp[(size_t)DIM * DIM];       // proj_w fp16
__device__ alignas(16) __half g_Q[(size_t)BB * HH * NN * DH]; // scaled q
__device__ alignas(16) __half g_K[(size_t)BB * HH * NN * DH];
__device__ alignas(16) __half g_V[(size_t)BB * HH * NN * DH];
__device__ alignas(16) __half g_AO[(size_t)MTOT * DIM];       // attn out [B,N,H*DH]
__device__ alignas(16) float  g_bias[(size_t)HH * NPR * NP];  // padded bias [12,256,208]

// ---------------- cp.async helpers ----------------
__device__ __forceinline__ void cpa16(void* dst, const void* src) {
    unsigned sa = (unsigned)__cvta_generic_to_shared(dst);
    asm volatile("cp.async.cg.shared.global [%0], [%1], 16;" :: "r"(sa), "l"(src));
}
#define CP_COMMIT() asm volatile("cp.async.commit_group;")
#define CP_WAIT(n)  asm volatile("cp.async.wait_group %0;" :: "n"(n))

// ---------------- fp32 -> fp16 convert ----------------
__global__ void f2h_kernel(const float* __restrict__ src, int n2, int which) {
    __half* dst = (which == 0) ? g_Xh : (which == 1) ? g_Wqkv : g_Wp;
    int i = blockIdx.x * blockDim.x + threadIdx.x;
    if (i < n2) {
        float2 v = reinterpret_cast<const float2*>(src)[i];
        reinterpret_cast<__half2*>(dst)[i] = __floats2half2_rn(v.x, v.y);
    }
}

// ---------------- expand bias into padded [12,256,208] fp32 ------------------
__global__ void bias_kernel(const float* __restrict__ tab, const int* __restrict__ ridx) {
    int idx = blockIdx.x * blockDim.x + threadIdx.x;
    const int TOT = HH * NPR * NP;
    if (idx >= TOT) return;
    int h = idx / (NPR * NP);
    int rem = idx - h * (NPR * NP);
    int r = rem / NP, c = rem - r * NP;
    float v = 0.0f;
    if (r < NN && c < NN) v = tab[ridx[r * NN + c] * HH + h];
    g_bias[idx] = v;
}

// ---------------- WMMA GEMM: C[M, Ncols] = A[M,768] * W[Ncols,768]^T --------
// 128x128 block tile, cp.async double-buffered, 8 warps x (64x32 out).
#define GBK 32
#define GNT (DIM / GBK)   // 24 k-steps

__global__ __launch_bounds__(256, 2)
void gemm_kernel(int mode, const float* __restrict__ bias, float* __restrict__ outf) {
    __shared__ alignas(16) char smraw[40960];
    __half* AsP[2] = { reinterpret_cast<__half*>(smraw),
                       reinterpret_cast<__half*>(smraw + 20480) };
    __half* BsP[2] = { reinterpret_cast<__half*>(smraw + 10240),
                       reinterpret_cast<__half*>(smraw + 30720) };
    float (*Cs)[72] = reinterpret_cast<float(*)[72]>(smraw);  // epilogue overlay

    const __half* A = (mode == 0) ? g_Xh : g_AO;
    const __half* W = (mode == 0) ? g_Wqkv : g_Wp;

    const int m0 = blockIdx.y * 128;
    const int n0 = blockIdx.x * 128;
    const int tid = threadIdx.x;
    const int wid = tid >> 5;
    const int wm = wid >> 2, wn = wid & 3;   // 2 x 4 warp grid; warp owns 64x32

    wmma::fragment<wmma::accumulator, 16, 16, 16, float> acc[4][2];
#pragma unroll
    for (int i = 0; i < 4; i++)
#pragma unroll
        for (int j = 0; j < 2; j++) wmma::fill_fragment(acc[i][j], 0.0f);

    auto prefetch = [&](int kt, int s) {
        const __half* Ab = A + (size_t)m0 * DIM + kt * GBK;
        const __half* Bb = W + (size_t)n0 * DIM + kt * GBK;
#pragma unroll
        for (int t = tid; t < 512; t += 256) {
            int r = t >> 2, c = t & 3;
            cpa16(AsP[s] + r * 40 + c * 8, Ab + (size_t)r * DIM + c * 8);
        }
#pragma unroll
        for (int t = tid; t < 512; t += 256) {
            int r = t >> 2, c = t & 3;
            cpa16(BsP[s] + r * 40 + c * 8, Bb + (size_t)r * DIM + c * 8);
        }
    };

    prefetch(0, 0);
    CP_COMMIT();

    for (int kt = 0; kt < GNT; kt++) {
        const int s = kt & 1;
        if (kt + 1 < GNT) {
            prefetch(kt + 1, 1 - s);
            CP_COMMIT();
            CP_WAIT(1);
        } else {
            CP_WAIT(0);
        }
        __syncthreads();
#pragma unroll
        for (int kk = 0; kk < GBK; kk += 16) {
            wmma::fragment<wmma::matrix_a, 16, 16, 16, __half, wmma::row_major> af[4];
            wmma::fragment<wmma::matrix_b, 16, 16, 16, __half, wmma::col_major> bf[2];
#pragma unroll
            for (int i = 0; i < 4; i++)
                wmma::load_matrix_sync(af[i], AsP[s] + (wm * 64 + i * 16) * 40 + kk, 40);
#pragma unroll
            for (int j = 0; j < 2; j++)
                wmma::load_matrix_sync(bf[j], BsP[s] + (wn * 32 + j * 16) * 40 + kk, 40);
#pragma unroll
            for (int i = 0; i < 4; i++)
#pragma unroll
                for (int j = 0; j < 2; j++)
                    wmma::mma_sync(acc[i][j], af[i], bf[j], acc[i][j]);
        }
        __syncthreads();
    }

#pragma unroll
    for (int half = 0; half < 2; half++) {
        if ((wn >> 1) == half) {
#pragma unroll
            for (int i = 0; i < 4; i++)
#pragma unroll
                for (int j = 0; j < 2; j++)
                    wmma::store_matrix_sync(&Cs[wm * 64 + i * 16][(wn & 1) * 32 + j * 16],
                                            acc[i][j], 72, wmma::mem_row_major);
        }
        __syncthreads();
        if (mode == 1) {
            for (int idx = tid; idx < 128 * 64; idx += 256) {
                int r = idx >> 6, c = idx & 63;
                int m = m0 + r, n = n0 + half * 64 + c;
                outf[(size_t)m * DIM + n] = Cs[r][c] + bias[n];
            }
        } else {
            for (int idx = tid; idx < 128 * 64; idx += 256) {
                int r = idx >> 6, c = idx & 63;
                int m = m0 + r, n = n0 + half * 64 + c;
                float v = Cs[r][c];
                int which = n / DIM;
                int rem = n - which * DIM;
                int h = rem >> 6, d = rem & 63;
                int b = m / NN, t = m - b * NN;
                size_t off = ((size_t)(b * HH + h) * NN + t) * DH + d;
                if (which == 0)      g_Q[off] = __float2half(v * 0.125f);  // * DH^-0.5
                else if (which == 1) g_K[off] = __float2half(v);
                else                 g_V[off] = __float2half(v);
            }
        }
        __syncthreads();
    }
}

// ---------------- fused attention: one CTA (512 thr) per (b, h) --------------
// smem: K[208][72]h, V[208][72]h, Q[64][72]h, S[64][208]f, P[64][208]h, rinv[64]f
#define SM_K   0
#define SM_V   29952
#define SM_Q   59904
#define SM_S   69120
#define SM_P   122368
#define SM_R   148992
#define SMEM_ATTN 149248

__global__ __launch_bounds__(512)
void attn_kernel() {
    extern __shared__ __align__(16) char sm[];
    __half* Ksm = reinterpret_cast<__half*>(sm + SM_K);
    __half* Vsm = reinterpret_cast<__half*>(sm + SM_V);
    __half* Qsm = reinterpret_cast<__half*>(sm + SM_Q);
    float*  Ssm = reinterpret_cast<float*>(sm + SM_S);
    __half* Psm = reinterpret_cast<__half*>(sm + SM_P);
    float*  Rinv = reinterpret_cast<float*>(sm + SM_R);

    const int bh = blockIdx.x;
    const int b = bh / HH, h = bh - b * HH;
    const __half* Kg = g_K + (size_t)bh * NN * DH;
    const __half* Vg = g_V + (size_t)bh * NN * DH;
    const __half* Qg = g_Q + (size_t)bh * NN * DH;
    const float* biasH = g_bias + (size_t)h * NPR * NP;
    const int tid = threadIdx.x, lane = tid & 31, wid = tid >> 5;

    // Load K, V (zero-pad rows 197..207)
    for (int idx = tid; idx < NP * 8; idx += 512) {
        int r = idx >> 3, c = idx & 7;
        uint4 z = make_uint4(0, 0, 0, 0);
        uint4 kv = (r < NN) ? *reinterpret_cast<const uint4*>(&Kg[r * DH + c * 8]) : z;
        uint4 vv = (r < NN) ? *reinterpret_cast<const uint4*>(&Vg[r * DH + c * 8]) : z;
        *reinterpret_cast<uint4*>(&Ksm[r * 72 + c * 8]) = kv;
        *reinterpret_cast<uint4*>(&Vsm[r * 72 + c * 8]) = vv;
    }

    for (int m0 = 0; m0 < NN; m0 += 64) {
        const int valid = min(64, NN - m0);
        // load Q chunk (zero-pad): 1 uint4 per thread
        {
            int r = tid >> 3, c = tid & 7;
            uint4 q = (r < valid)
                ? *reinterpret_cast<const uint4*>(&Qg[(m0 + r) * DH + c * 8])
                : make_uint4(0, 0, 0, 0);
            *reinterpret_cast<uint4*>(&Qsm[r * 72 + c * 8]) = q;
        }
        __syncthreads();

        // S = bias + Q K^T  (4 x 13 tiles of 16x16); bias preloads accumulator
        for (int t = wid; t < 52; t += 16) {
            int rt = t & 3, ct = t >> 2;
            wmma::fragment<wmma::accumulator, 16, 16, 16, float> c;
            wmma::load_matrix_sync(c, biasH + (size_t)(m0 + rt * 16) * NP + ct * 16,
                                   NP, wmma::mem_row_major);
#pragma unroll
            for (int kk = 0; kk < 64; kk += 16) {
                wmma::fragment<wmma::matrix_a, 16, 16, 16, __half, wmma::row_major> a;
                wmma::fragment<wmma::matrix_b, 16, 16, 16, __half, wmma::col_major> bb;
                wmma::load_matrix_sync(a, Qsm + rt * 16 * 72 + kk, 72);
                wmma::load_matrix_sync(bb, Ksm + ct * 16 * 72 + kk, 72);
                wmma::mma_sync(c, a, bb, c);
            }
            wmma::store_matrix_sync(Ssm + rt * 16 * NP + ct * 16, c, NP,
                                    wmma::mem_row_major);
        }
        __syncthreads();

        // softmax: warp handles 4 rows; P holds un-normalized exp
        {
            int r0 = wid * 4;
#pragma unroll
            for (int rr = 0; rr < 4; rr++) {
                int r = r0 + rr;
                float mx = -1e30f;
                for (int c = lane; c < NN; c += 32)
                    mx = fmaxf(mx, Ssm[r * NP + c]);
#pragma unroll
                for (int o = 16; o; o >>= 1) mx = fmaxf(mx, __shfl_xor_sync(~0u, mx, o));
                float s = 0.0f;
                for (int c = lane; c < NN; c += 32) {
                    float e = __expf(Ssm[r * NP + c] - mx);
                    s += e;
                    Psm[r * NP + c] = __float2half(e);
                }
#pragma unroll
                for (int o = 16; o; o >>= 1) s += __shfl_xor_sync(~0u, s, o);
                if (lane == 0) Rinv[r] = 1.0f / s;
                if (lane < NP - NN) Psm[r * NP + NN + lane] = __float2half(0.0f);
            }
        }
        __syncthreads();

        // O = P V  (4 x 4 tiles), accumulate fp32, store into Ssm as [64][72]
        for (int t = wid; t < 16; t += 16) {
            int rt = t & 3, ct = t >> 2;
            wmma::fragment<wmma::accumulator, 16, 16, 16, float> c;
            wmma::fill_fragment(c, 0.0f);
#pragma unroll
            for (int kk = 0; kk < 13; kk++) {
                wmma::fragment<wmma::matrix_a, 16, 16, 16, __half, wmma::row_major> a;
                wmma::fragment<wmma::matrix_b, 16, 16, 16, __half, wmma::row_major> bb;
                wmma::load_matrix_sync(a, Psm + rt * 16 * NP + kk * 16, NP);
                wmma::load_matrix_sync(bb, Vsm + kk * 16 * 72 + ct * 16, 72);
                wmma::mma_sync(c, a, bb, c);
            }
            wmma::store_matrix_sync(Ssm + rt * 16 * 72 + ct * 16, c, 72,
                                    wmma::mem_row_major);
        }
        __syncthreads();

        // write out with per-row normalization
        for (int idx = tid; idx < 64 * 64; idx += 512) {
            int r = idx >> 6, d = idx & 63;
            if (r < valid) {
                float v = Ssm[r * 72 + d] * Rinv[r];
                g_AO[((size_t)(b * NN + m0 + r) * HH + h) * DH + d] = __float2half(v);
            }
        }
        __syncthreads();
    }
}

// ---------------- launch ----------------
extern "C" void kernel_launch(void* const* d_in, const int* in_sizes, int n_in,
                              void* d_out, int out_size) {
    const float* x     = (const float*)d_in[0];
    const float* qkvw  = (const float*)d_in[1];
    const float* projw = (const float*)d_in[2];
    const float* projb = (const float*)d_in[3];
    const float* btab  = (const float*)d_in[4];
    const int*   ridx  = (const int*)d_in[5];
    float* out = (float*)d_out;

    cudaFuncSetAttribute(attn_kernel, cudaFuncAttributeMaxDynamicSharedMemorySize,
                         SMEM_ATTN);

    const int nx = MTOT * DIM;          // 19,365,888
    const int nw1 = 3 * DIM * DIM;      // 1,769,472
    const int nw2 = DIM * DIM;          // 589,824

    // Launch order: profiled slot (0-based idx 3) = QKV GEMM
    const int nb = HH * NPR * NP;
    bias_kernel<<<(nb + 255) / 256, 256>>>(btab, ridx);            // 0
    f2h_kernel<<<(nx / 2 + 255) / 256, 256>>>(x, nx / 2, 0);       // 1
    f2h_kernel<<<(nw1 / 2 + 255) / 256, 256>>>(qkvw, nw1 / 2, 1);  // 2

    // QKV: M=25216, N=2304                                         // 3 (profiled)
    gemm_kernel<<<dim3(3 * DIM / 128, MTOT / 128), 256>>>(0, nullptr, nullptr);

    f2h_kernel<<<(nw2 / 2 + 255) / 256, 256>>>(projw, nw2 / 2, 2); // 4

    // fused attention                                              // 5
    attn_kernel<<<BB * HH, 512, SMEM_ATTN>>>();

    // proj: M=25216, N=768                                         // 6
    gemm_kernel<<<dim3(DIM / 128, MTOT / 128), 256>>>(1, projb, out);
}

// round 5
// speedup vs baseline: 1.5789x; 1.0543x over previous
#include <cuda_runtime.h>
#include <cuda_fp16.h>
#include <mma.h>

using namespace nvcuda;

// Problem constants
#define BB   128
#define NN   197
#define HH   12
#define DH   64
#define DIM  768
#define MTOT (BB * NN)          // 25216 (divisible by 128)
#define TABLE 730
#define NP   208                // padded N (cols) for bias / S tiles
#define NPR  256                // padded N (rows) for bias

// ---------------- scratch (device globals; no allocations allowed) ----------
__device__ alignas(16) __half g_Xh[(size_t)MTOT * DIM];      // x in fp16
__device__ alignas(16) __half g_Wqkv[(size_t)3 * DIM * DIM]; // qkv_w fp16
__device__ alignas(16) __half g_Wp[(size_t)DIM * DIM];       // proj_w fp16
__device__ alignas(16) __half g_Q[(size_t)BB * HH * NN * DH]; // scaled q
__device__ alignas(16) __half g_K[(size_t)BB * HH * NN * DH];
__device__ alignas(16) __half g_V[(size_t)BB * HH * NN * DH];
__device__ alignas(16) __half g_AO[(size_t)MTOT * DIM];       // attn out [B,N,H*DH]
__device__ alignas(16) float  g_bias[(size_t)HH * NPR * NP];  // padded bias [12,256,208]

// ---------------- cp.async helpers ----------------
__device__ __forceinline__ void cpa16(void* dst, const void* src) {
    unsigned sa = (unsigned)__cvta_generic_to_shared(dst);
    asm volatile("cp.async.cg.shared.global [%0], [%1], 16;" :: "r"(sa), "l"(src));
}
#define CP_COMMIT() asm volatile("cp.async.commit_group;")
#define CP_WAIT(n)  asm volatile("cp.async.wait_group %0;" :: "n"(n))

// ---------------- fused fp32 -> fp16 convert (x, qkv_w, proj_w) -------------
#define NX2  (MTOT * DIM / 2)
#define NW12 (3 * DIM * DIM / 2)
#define NW22 (DIM * DIM / 2)
__global__ void f2h_all(const float* __restrict__ x, const float* __restrict__ qkvw,
                        const float* __restrict__ projw) {
    int i = blockIdx.x * blockDim.x + threadIdx.x;
    if (i < NX2) {
        float2 v = reinterpret_cast<const float2*>(x)[i];
        reinterpret_cast<__half2*>(g_Xh)[i] = __floats2half2_rn(v.x, v.y);
    } else if (i < NX2 + NW12) {
        int j = i - NX2;
        float2 v = reinterpret_cast<const float2*>(qkvw)[j];
        reinterpret_cast<__half2*>(g_Wqkv)[j] = __floats2half2_rn(v.x, v.y);
    } else if (i < NX2 + NW12 + NW22) {
        int j = i - NX2 - NW12;
        float2 v = reinterpret_cast<const float2*>(projw)[j];
        reinterpret_cast<__half2*>(g_Wp)[j] = __floats2half2_rn(v.x, v.y);
    }
}

// ---------------- expand bias into padded [12,256,208] fp32 ------------------
__global__ void bias_kernel(const float* __restrict__ tab, const int* __restrict__ ridx) {
    int idx = blockIdx.x * blockDim.x + threadIdx.x;
    const int TOT = HH * NPR * NP;
    if (idx >= TOT) return;
    int h = idx / (NPR * NP);
    int rem = idx - h * (NPR * NP);
    int r = rem / NP, c = rem - r * NP;
    float v = 0.0f;
    if (r < NN && c < NN) v = tab[ridx[r * NN + c] * HH + h];
    g_bias[idx] = v;
}

// ---------------- WMMA GEMM: C[M, Ncols] = A[M,768] * W[Ncols,768]^T --------
// 128x128 block tile, cp.async 3-stage pipeline (single barrier per k-step),
// 8 warps x (64x32 out).
#define GBK 32
#define GNT (DIM / GBK)   // 24 k-steps
#define GSTG 3

__global__ __launch_bounds__(256, 2)
void gemm_kernel(int mode, const float* __restrict__ bias, float* __restrict__ outf) {
    __shared__ alignas(16) char smraw[GSTG * 20480];
    __half* AsP[GSTG];
    __half* BsP[GSTG];
#pragma unroll
    for (int s = 0; s < GSTG; s++) {
        AsP[s] = reinterpret_cast<__half*>(smraw + s * 20480);
        BsP[s] = reinterpret_cast<__half*>(smraw + s * 20480 + 10240);
    }
    float (*Cs)[72] = reinterpret_cast<float(*)[72]>(smraw);  // epilogue overlay

    const __half* A = (mode == 0) ? g_Xh : g_AO;
    const __half* W = (mode == 0) ? g_Wqkv : g_Wp;

    const int m0 = blockIdx.y * 128;
    const int n0 = blockIdx.x * 128;
    const int tid = threadIdx.x;
    const int wid = tid >> 5;
    const int wm = wid >> 2, wn = wid & 3;   // 2 x 4 warp grid; warp owns 64x32

    wmma::fragment<wmma::accumulator, 16, 16, 16, float> acc[4][2];
#pragma unroll
    for (int i = 0; i < 4; i++)
#pragma unroll
        for (int j = 0; j < 2; j++) wmma::fill_fragment(acc[i][j], 0.0f);

    auto prefetch = [&](int kt, int s) {
        const __half* Ab = A + (size_t)m0 * DIM + kt * GBK;
        const __half* Bb = W + (size_t)n0 * DIM + kt * GBK;
#pragma unroll
        for (int t = tid; t < 512; t += 256) {
            int r = t >> 2, c = t & 3;
            cpa16(AsP[s] + r * 40 + c * 8, Ab + (size_t)r * DIM + c * 8);
        }
#pragma unroll
        for (int t = tid; t < 512; t += 256) {
            int r = t >> 2, c = t & 3;
            cpa16(BsP[s] + r * 40 + c * 8, Bb + (size_t)r * DIM + c * 8);
        }
    };

    prefetch(0, 0);
    CP_COMMIT();
    prefetch(1, 1);
    CP_COMMIT();

    for (int kt = 0; kt < GNT; kt++) {
        const int s = kt % GSTG;
        CP_WAIT(1);          // stage kt resident
        __syncthreads();     // all warps past previous compute; stage visible
        if (kt + 2 < GNT) {
            prefetch(kt + 2, (kt + 2) % GSTG);
            CP_COMMIT();
        }
#pragma unroll
        for (int kk = 0; kk < GBK; kk += 16) {
            wmma::fragment<wmma::matrix_a, 16, 16, 16, __half, wmma::row_major> af[4];
            wmma::fragment<wmma::matrix_b, 16, 16, 16, __half, wmma::col_major> bf[2];
#pragma unroll
            for (int i = 0; i < 4; i++)
                wmma::load_matrix_sync(af[i], AsP[s] + (wm * 64 + i * 16) * 40 + kk, 40);
#pragma unroll
            for (int j = 0; j < 2; j++)
                wmma::load_matrix_sync(bf[j], BsP[s] + (wn * 32 + j * 16) * 40 + kk, 40);
#pragma unroll
            for (int i = 0; i < 4; i++)
#pragma unroll
                for (int j = 0; j < 2; j++)
                    wmma::mma_sync(acc[i][j], af[i], bf[j], acc[i][j]);
        }
    }
    __syncthreads();

#pragma unroll
    for (int half = 0; half < 2; half++) {
        if ((wn >> 1) == half) {
#pragma unroll
            for (int i = 0; i < 4; i++)
#pragma unroll
                for (int j = 0; j < 2; j++)
                    wmma::store_matrix_sync(&Cs[wm * 64 + i * 16][(wn & 1) * 32 + j * 16],
                                            acc[i][j], 72, wmma::mem_row_major);
        }
        __syncthreads();
        if (mode == 1) {
            for (int idx = tid; idx < 128 * 64; idx += 256) {
                int r = idx >> 6, c = idx & 63;
                int m = m0 + r, n = n0 + half * 64 + c;
                outf[(size_t)m * DIM + n] = Cs[r][c] + bias[n];
            }
        } else {
            for (int idx = tid; idx < 128 * 64; idx += 256) {
                int r = idx >> 6, c = idx & 63;
                int m = m0 + r, n = n0 + half * 64 + c;
                float v = Cs[r][c];
                int which = n / DIM;
                int rem = n - which * DIM;
                int h = rem >> 6, d = rem & 63;
                int b = m / NN, t = m - b * NN;
                size_t off = ((size_t)(b * HH + h) * NN + t) * DH + d;
                if (which == 0)      g_Q[off] = __float2half(v * 0.125f);  // * DH^-0.5
                else if (which == 1) g_K[off] = __float2half(v);
                else                 g_V[off] = __float2half(v);
            }
        }
        __syncthreads();
    }
}

// ---------------- fused attention: 256 threads, 32-row chunks, 2 CTAs/SM -----
// smem: K[208][72]h, V[208][72]h, Q[32][72]h, S[32][208]f, P[32][208]h, rinv[32]f
#define SM_K   0
#define SM_V   29952
#define SM_Q   59904
#define SM_S   64512
#define SM_P   91136
#define SM_R   104448
#define SMEM_ATTN 104576

__global__ __launch_bounds__(256, 2)
void attn_kernel() {
    extern __shared__ __align__(16) char sm[];
    __half* Ksm = reinterpret_cast<__half*>(sm + SM_K);
    __half* Vsm = reinterpret_cast<__half*>(sm + SM_V);
    __half* Qsm = reinterpret_cast<__half*>(sm + SM_Q);
    float*  Ssm = reinterpret_cast<float*>(sm + SM_S);
    __half* Psm = reinterpret_cast<__half*>(sm + SM_P);
    float*  Rinv = reinterpret_cast<float*>(sm + SM_R);

    const int bh = blockIdx.x;
    const int b = bh / HH, h = bh - b * HH;
    const __half* Kg = g_K + (size_t)bh * NN * DH;
    const __half* Vg = g_V + (size_t)bh * NN * DH;
    const __half* Qg = g_Q + (size_t)bh * NN * DH;
    const float* biasH = g_bias + (size_t)h * NPR * NP;
    const int tid = threadIdx.x, lane = tid & 31, wid = tid >> 5;

    // Load K, V (zero-pad rows 197..207)
    for (int idx = tid; idx < NP * 8; idx += 256) {
        int r = idx >> 3, c = idx & 7;
        uint4 z = make_uint4(0, 0, 0, 0);
        uint4 kv = (r < NN) ? *reinterpret_cast<const uint4*>(&Kg[r * DH + c * 8]) : z;
        uint4 vv = (r < NN) ? *reinterpret_cast<const uint4*>(&Vg[r * DH + c * 8]) : z;
        *reinterpret_cast<uint4*>(&Ksm[r * 72 + c * 8]) = kv;
        *reinterpret_cast<uint4*>(&Vsm[r * 72 + c * 8]) = vv;
    }

    for (int m0 = 0; m0 < NN; m0 += 32) {
        const int valid = min(32, NN - m0);
        // load Q chunk (zero-pad): 32x8 uint4 = exactly 1 per thread
        {
            int r = tid >> 3, c = tid & 7;
            uint4 q = (r < valid)
                ? *reinterpret_cast<const uint4*>(&Qg[(m0 + r) * DH + c * 8])
                : make_uint4(0, 0, 0, 0);
            *reinterpret_cast<uint4*>(&Qsm[r * 72 + c * 8]) = q;
        }
        __syncthreads();

        // S = bias + Q K^T  (2 x 13 tiles of 16x16); bias preloads accumulator
        for (int t = wid; t < 26; t += 8) {
            int rt = t & 1, ct = t >> 1;
            wmma::fragment<wmma::accumulator, 16, 16, 16, float> c;
            wmma::load_matrix_sync(c, biasH + (size_t)(m0 + rt * 16) * NP + ct * 16,
                                   NP, wmma::mem_row_major);
#pragma unroll
            for (int kk = 0; kk < 64; kk += 16) {
                wmma::fragment<wmma::matrix_a, 16, 16, 16, __half, wmma::row_major> a;
                wmma::fragment<wmma::matrix_b, 16, 16, 16, __half, wmma::col_major> bb;
                wmma::load_matrix_sync(a, Qsm + rt * 16 * 72 + kk, 72);
                wmma::load_matrix_sync(bb, Ksm + ct * 16 * 72 + kk, 72);
                wmma::mma_sync(c, a, bb, c);
            }
            wmma::store_matrix_sync(Ssm + rt * 16 * NP + ct * 16, c, NP,
                                    wmma::mem_row_major);
        }
        __syncthreads();

        // softmax: warp handles 4 rows; P holds un-normalized exp
        {
            int r0 = wid * 4;
#pragma unroll
            for (int rr = 0; rr < 4; rr++) {
                int r = r0 + rr;
                float mx = -1e30f;
                for (int c = lane; c < NN; c += 32)
                    mx = fmaxf(mx, Ssm[r * NP + c]);
#pragma unroll
                for (int o = 16; o; o >>= 1) mx = fmaxf(mx, __shfl_xor_sync(~0u, mx, o));
                float s = 0.0f;
                for (int c = lane; c < NN; c += 32) {
                    float e = __expf(Ssm[r * NP + c] - mx);
                    s += e;
                    Psm[r * NP + c] = __float2half(e);
                }
#pragma unroll
                for (int o = 16; o; o >>= 1) s += __shfl_xor_sync(~0u, s, o);
                if (lane == 0) Rinv[r] = 1.0f / s;
                if (lane < NP - NN) Psm[r * NP + NN + lane] = __float2half(0.0f);
            }
        }
        __syncthreads();

        // O = P V  (2 x 4 tiles = 8, one per warp), store into Ssm as [32][72]
        {
            int rt = wid & 1, ct = wid >> 1;
            wmma::fragment<wmma::accumulator, 16, 16, 16, float> c;
            wmma::fill_fragment(c, 0.0f);
#pragma unroll
            for (int kk = 0; kk < 13; kk++) {
                wmma::fragment<wmma::matrix_a, 16, 16, 16, __half, wmma::row_major> a;
                wmma::fragment<wmma::matrix_b, 16, 16, 16, __half, wmma::row_major> bb;
                wmma::load_matrix_sync(a, Psm + rt * 16 * NP + kk * 16, NP);
                wmma::load_matrix_sync(bb, Vsm + kk * 16 * 72 + ct * 16, 72);
                wmma::mma_sync(c, a, bb, c);
            }
            wmma::store_matrix_sync(Ssm + rt * 16 * 72 + ct * 16, c, 72,
                                    wmma::mem_row_major);
        }
        __syncthreads();

        // write out with per-row normalization: 2048/256 = 8 per thread
        for (int idx = tid; idx < 32 * 64; idx += 256) {
            int r = idx >> 6, d = idx & 63;
            if (r < valid) {
                float v = Ssm[r * 72 + d] * Rinv[r];
                g_AO[((size_t)(b * NN + m0 + r) * HH + h) * DH + d] = __float2half(v);
            }
        }
        __syncthreads();
    }
}

// ---------------- launch ----------------
extern "C" void kernel_launch(void* const* d_in, const int* in_sizes, int n_in,
                              void* d_out, int out_size) {
    const float* x     = (const float*)d_in[0];
    const float* qkvw  = (const float*)d_in[1];
    const float* projw = (const float*)d_in[2];
    const float* projb = (const float*)d_in[3];
    const float* btab  = (const float*)d_in[4];
    const int*   ridx  = (const int*)d_in[5];
    float* out = (float*)d_out;

    cudaFuncSetAttribute(attn_kernel, cudaFuncAttributeMaxDynamicSharedMemorySize,
                         SMEM_ATTN);

    // Launch order: profiled slot (0-based idx 3) = attn_kernel
    const int ncv = NX2 + NW12 + NW22;
    f2h_all<<<(ncv + 255) / 256, 256>>>(x, qkvw, projw);           // 0

    const int nb = HH * NPR * NP;
    bias_kernel<<<(nb + 255) / 256, 256>>>(btab, ridx);            // 1

    // QKV: M=25216, N=2304                                         // 2
    gemm_kernel<<<dim3(3 * DIM / 128, MTOT / 128), 256>>>(0, nullptr, nullptr);

    // fused attention                                              // 3 (profiled)
    attn_kernel<<<BB * HH, 256, SMEM_ATTN>>>();

    // proj: M=25216, N=768                                         // 4
    gemm_kernel<<<dim3(DIM / 128, MTOT / 128), 256>>>(1, projb, out);
}

// round 7
// speedup vs baseline: 1.9596x; 1.2411x over previous
#include <cuda_runtime.h>
#include <cuda_fp16.h>
#include <mma.h>

using namespace nvcuda;

// Problem constants
#define BB   128
#define NN   197
#define HH   12
#define DH   64
#define DIM  768
#define MTOT (BB * NN)          // 25216
#define TABLE 730
#define NP   208                // padded cols for bias / S
#define NPR  256                // padded rows for bias

// ---------------- scratch (device globals; no allocations allowed) ----------
__device__ alignas(16) __half g_Xh[(size_t)MTOT * DIM];
__device__ alignas(16) __half g_Wqkv[(size_t)3 * DIM * DIM];
__device__ alignas(16) __half g_Wp[(size_t)DIM * DIM];
__device__ alignas(16) __half g_Q[(size_t)BB * HH * NN * DH];
__device__ alignas(16) __half g_K[(size_t)BB * HH * NN * DH];
__device__ alignas(16) __half g_V[(size_t)BB * HH * NN * DH];
__device__ alignas(16) __half g_AO[(size_t)MTOT * DIM];
__device__ alignas(16) float  g_bias[(size_t)HH * NPR * NP];

// ---------------- cp.async helpers ----------------
__device__ __forceinline__ void cpa16(void* dst, const void* src) {
    unsigned sa = (unsigned)__cvta_generic_to_shared(dst);
    asm volatile("cp.async.cg.shared.global [%0], [%1], 16;" :: "r"(sa), "l"(src));
}
#define CP_COMMIT() asm volatile("cp.async.commit_group;")
#define CP_WAIT(n)  asm volatile("cp.async.wait_group %0;" :: "n"(n))

// ---------------- bit-cast helpers ----------------
__device__ __forceinline__ unsigned h2_as_u(__half2 h) {
    return *reinterpret_cast<unsigned*>(&h);
}

// ---------------- mma / ldmatrix helpers ----------------
__device__ __forceinline__ void ldsm4(unsigned& r0, unsigned& r1, unsigned& r2,
                                      unsigned& r3, const void* p) {
    unsigned a = (unsigned)__cvta_generic_to_shared(p);
    asm volatile("ldmatrix.sync.aligned.m8n8.x4.shared.b16 {%0,%1,%2,%3}, [%4];"
                 : "=r"(r0), "=r"(r1), "=r"(r2), "=r"(r3) : "r"(a));
}
__device__ __forceinline__ void ldsm4t(unsigned& r0, unsigned& r1, unsigned& r2,
                                       unsigned& r3, const void* p) {
    unsigned a = (unsigned)__cvta_generic_to_shared(p);
    asm volatile("ldmatrix.sync.aligned.m8n8.x4.trans.shared.b16 {%0,%1,%2,%3}, [%4];"
                 : "=r"(r0), "=r"(r1), "=r"(r2), "=r"(r3) : "r"(a));
}
__device__ __forceinline__ void mma16816(float* c, const unsigned* a,
                                         unsigned b0, unsigned b1) {
    asm volatile(
        "mma.sync.aligned.m16n8k16.row.col.f32.f16.f16.f32 "
        "{%0,%1,%2,%3}, {%4,%5,%6,%7}, {%8,%9}, {%0,%1,%2,%3};"
        : "+f"(c[0]), "+f"(c[1]), "+f"(c[2]), "+f"(c[3])
        : "r"(a[0]), "r"(a[1]), "r"(a[2]), "r"(a[3]), "r"(b0), "r"(b1));
}

// ---------------- fused fp32 -> fp16 convert ----------------
#define NX2  (MTOT * DIM / 2)
#define NW12 (3 * DIM * DIM / 2)
#define NW22 (DIM * DIM / 2)
__global__ void f2h_all(const float* __restrict__ x, const float* __restrict__ qkvw,
                        const float* __restrict__ projw) {
    int i = blockIdx.x * blockDim.x + threadIdx.x;
    if (i < NX2) {
        float2 v = reinterpret_cast<const float2*>(x)[i];
        reinterpret_cast<__half2*>(g_Xh)[i] = __floats2half2_rn(v.x, v.y);
    } else if (i < NX2 + NW12) {
        int j = i - NX2;
        float2 v = reinterpret_cast<const float2*>(qkvw)[j];
        reinterpret_cast<__half2*>(g_Wqkv)[j] = __floats2half2_rn(v.x, v.y);
    } else if (i < NX2 + NW12 + NW22) {
        int j = i - NX2 - NW12;
        float2 v = reinterpret_cast<const float2*>(projw)[j];
        reinterpret_cast<__half2*>(g_Wp)[j] = __floats2half2_rn(v.x, v.y);
    }
}

// ---------------- expand bias into padded [12,256,208] fp32 ------------------
__global__ void bias_kernel(const float* __restrict__ tab, const int* __restrict__ ridx) {
    int idx = blockIdx.x * blockDim.x + threadIdx.x;
    const int TOT = HH * NPR * NP;
    if (idx >= TOT) return;
    int h = idx / (NPR * NP);
    int rem = idx - h * (NPR * NP);
    int r = rem / NP, c = rem - r * NP;
    float v = 0.0f;
    if (r < NN && c < NN) v = tab[ridx[r * NN + c] * HH + h];
    g_bias[idx] = v;
}

// ---------------- WMMA GEMM (unchanged) --------------------------------------
#define GBK 32
#define GNT (DIM / GBK)
#define GSTG 3

__global__ __launch_bounds__(256, 2)
void gemm_kernel(int mode, const float* __restrict__ bias, float* __restrict__ outf) {
    __shared__ alignas(16) char smraw[GSTG * 20480];
    __half* AsP[GSTG];
    __half* BsP[GSTG];
#pragma unroll
    for (int s = 0; s < GSTG; s++) {
        AsP[s] = reinterpret_cast<__half*>(smraw + s * 20480);
        BsP[s] = reinterpret_cast<__half*>(smraw + s * 20480 + 10240);
    }
    float (*Cs)[72] = reinterpret_cast<float(*)[72]>(smraw);

    const __half* A = (mode == 0) ? g_Xh : g_AO;
    const __half* W = (mode == 0) ? g_Wqkv : g_Wp;

    const int m0 = blockIdx.y * 128;
    const int n0 = blockIdx.x * 128;
    const int tid = threadIdx.x;
    const int wid = tid >> 5;
    const int wm = wid >> 2, wn = wid & 3;

    wmma::fragment<wmma::accumulator, 16, 16, 16, float> acc[4][2];
#pragma unroll
    for (int i = 0; i < 4; i++)
#pragma unroll
        for (int j = 0; j < 2; j++) wmma::fill_fragment(acc[i][j], 0.0f);

    auto prefetch = [&](int kt, int s) {
        const __half* Ab = A + (size_t)m0 * DIM + kt * GBK;
        const __half* Bb = W + (size_t)n0 * DIM + kt * GBK;
#pragma unroll
        for (int t = tid; t < 512; t += 256) {
            int r = t >> 2, c = t & 3;
            cpa16(AsP[s] + r * 40 + c * 8, Ab + (size_t)r * DIM + c * 8);
        }
#pragma unroll
        for (int t = tid; t < 512; t += 256) {
            int r = t >> 2, c = t & 3;
            cpa16(BsP[s] + r * 40 + c * 8, Bb + (size_t)r * DIM + c * 8);
        }
    };

    prefetch(0, 0);
    CP_COMMIT();
    prefetch(1, 1);
    CP_COMMIT();

    for (int kt = 0; kt < GNT; kt++) {
        const int s = kt % GSTG;
        CP_WAIT(1);
        __syncthreads();
        if (kt + 2 < GNT) {
            prefetch(kt + 2, (kt + 2) % GSTG);
            CP_COMMIT();
        }
#pragma unroll
        for (int kk = 0; kk < GBK; kk += 16) {
            wmma::fragment<wmma::matrix_a, 16, 16, 16, __half, wmma::row_major> af[4];
            wmma::fragment<wmma::matrix_b, 16, 16, 16, __half, wmma::col_major> bf[2];
#pragma unroll
            for (int i = 0; i < 4; i++)
                wmma::load_matrix_sync(af[i], AsP[s] + (wm * 64 + i * 16) * 40 + kk, 40);
#pragma unroll
            for (int j = 0; j < 2; j++)
                wmma::load_matrix_sync(bf[j], BsP[s] + (wn * 32 + j * 16) * 40 + kk, 40);
#pragma unroll
            for (int i = 0; i < 4; i++)
#pragma unroll
                for (int j = 0; j < 2; j++)
                    wmma::mma_sync(acc[i][j], af[i], bf[j], acc[i][j]);
        }
    }
    __syncthreads();

#pragma unroll
    for (int half = 0; half < 2; half++) {
        if ((wn >> 1) == half) {
#pragma unroll
            for (int i = 0; i < 4; i++)
#pragma unroll
                for (int j = 0; j < 2; j++)
                    wmma::store_matrix_sync(&Cs[wm * 64 + i * 16][(wn & 1) * 32 + j * 16],
                                            acc[i][j], 72, wmma::mem_row_major);
        }
        __syncthreads();
        if (mode == 1) {
            for (int idx = tid; idx < 128 * 64; idx += 256) {
                int r = idx >> 6, c = idx & 63;
                int m = m0 + r, n = n0 + half * 64 + c;
                outf[(size_t)m * DIM + n] = Cs[r][c] + bias[n];
            }
        } else {
            for (int idx = tid; idx < 128 * 64; idx += 256) {
                int r = idx >> 6, c = idx & 63;
                int m = m0 + r, n = n0 + half * 64 + c;
                float v = Cs[r][c];
                int which = n / DIM;
                int rem = n - which * DIM;
                int h = rem >> 6, d = rem & 63;
                int b = m / NN, t = m - b * NN;
                size_t off = ((size_t)(b * HH + h) * NN + t) * DH + d;
                if (which == 0)      g_Q[off] = __float2half(v * 0.125f);
                else if (which == 1) g_K[off] = __float2half(v);
                else                 g_V[off] = __float2half(v);
            }
        }
        __syncthreads();
    }
}

// ---------------- FA2-style attention: registers only for S/P ---------------
// smem: K[208][72]h + V[208][72]h = 59904 B. One CTA (256 thr) per (b,h).
// Warp w handles 16-row strips {w, w+8} of 13; S strip (16x208) in regs.
#define SMEM_ATTN (2 * NP * 72 * 2)

__global__ __launch_bounds__(256)
void attn_kernel() {
    extern __shared__ __align__(16) char sm[];
    __half* Ksm = reinterpret_cast<__half*>(sm);
    __half* Vsm = reinterpret_cast<__half*>(sm + NP * 72 * 2);

    const int bh = blockIdx.x;
    const int b = bh / HH, h = bh - b * HH;
    const __half* Kg = g_K + (size_t)bh * NN * DH;
    const __half* Vg = g_V + (size_t)bh * NN * DH;
    const __half* Qg = g_Q + (size_t)bh * NN * DH;
    const float* biasH = g_bias + (size_t)h * NPR * NP;
    const int tid = threadIdx.x, lane = tid & 31, wid = tid >> 5;

    // stage K, V (zero-pad rows 197..207)
    for (int idx = tid; idx < NP * 8; idx += 256) {
        int r = idx >> 3, c = idx & 7;
        uint4 z = make_uint4(0, 0, 0, 0);
        uint4 kv = (r < NN) ? *reinterpret_cast<const uint4*>(&Kg[r * DH + c * 8]) : z;
        uint4 vv = (r < NN) ? *reinterpret_cast<const uint4*>(&Vg[r * DH + c * 8]) : z;
        *reinterpret_cast<uint4*>(&Ksm[r * 72 + c * 8]) = kv;
        *reinterpret_cast<uint4*>(&Vsm[r * 72 + c * 8]) = vv;
    }
    __syncthreads();

    const int qd = lane >> 2;       // quad row offset 0..7
    const int ql = lane & 3;        // quad lane 0..3

    for (int strip = wid; strip < 13; strip += 8) {
        const int r0 = strip * 16;
        const int row0 = r0 + qd;          // this thread's low row
        const int row1 = row0 + 8;         // high row

        // ---- load Q A-fragments straight from gmem (rows clamped) ----
        unsigned a[4][4];
        {
            const __half2* Qa = reinterpret_cast<const __half2*>(
                Qg + (size_t)min(row0, NN - 1) * DH);
            const __half2* Qb = reinterpret_cast<const __half2*>(
                Qg + (size_t)min(row1, NN - 1) * DH);
#pragma unroll
            for (int kk = 0; kk < 4; kk++) {
                a[kk][0] = reinterpret_cast<const unsigned*>(Qa)[kk * 8 + ql];
                a[kk][1] = reinterpret_cast<const unsigned*>(Qb)[kk * 8 + ql];
                a[kk][2] = reinterpret_cast<const unsigned*>(Qa)[kk * 8 + 4 + ql];
                a[kk][3] = reinterpret_cast<const unsigned*>(Qb)[kk * 8 + 4 + ql];
            }
        }

        // ---- init accumulators with bias ----
        float c[25][4];
#pragma unroll
        for (int nb = 0; nb < 25; nb++) {
            float2 b0 = *reinterpret_cast<const float2*>(
                biasH + (size_t)row0 * NP + nb * 8 + ql * 2);
            float2 b1 = *reinterpret_cast<const float2*>(
                biasH + (size_t)row1 * NP + nb * 8 + ql * 2);
            c[nb][0] = b0.x; c[nb][1] = b0.y; c[nb][2] = b1.x; c[nb][3] = b1.y;
        }

        // ---- S = Q K^T + bias ----
        const int ln = (lane >> 4) * 8 + (lane & 7);
        const int lk = ((lane >> 3) & 1) * 8;
#pragma unroll
        for (int np = 0; np < 13; np++) {
#pragma unroll
            for (int kk = 0; kk < 4; kk++) {
                unsigned b0, b1, b2, b3;
                ldsm4(b0, b1, b2, b3, Ksm + (np * 16 + ln) * 72 + kk * 16 + lk);
                mma16816(c[2 * np], a[kk], b0, b1);
                if (np < 12) mma16816(c[2 * np + 1], a[kk], b2, b3);
            }
        }

        // ---- mask cols >= 197 (only nb 24: cols 192..199) ----
        {
            int c0 = 192 + ql * 2;
            if (c0 >= NN)     { c[24][0] = -1e30f; c[24][2] = -1e30f; }
            if (c0 + 1 >= NN) { c[24][1] = -1e30f; c[24][3] = -1e30f; }
        }

        // ---- softmax on fragments ----
        float m0 = -1e30f, m1 = -1e30f;
#pragma unroll
        for (int nb = 0; nb < 25; nb++) {
            m0 = fmaxf(m0, fmaxf(c[nb][0], c[nb][1]));
            m1 = fmaxf(m1, fmaxf(c[nb][2], c[nb][3]));
        }
        m0 = fmaxf(m0, __shfl_xor_sync(~0u, m0, 1));
        m0 = fmaxf(m0, __shfl_xor_sync(~0u, m0, 2));
        m1 = fmaxf(m1, __shfl_xor_sync(~0u, m1, 1));
        m1 = fmaxf(m1, __shfl_xor_sync(~0u, m1, 2));

        float s0 = 0.0f, s1 = 0.0f;
        unsigned p[25];
#pragma unroll
        for (int nb = 0; nb < 25; nb++) {
            float e0 = __expf(c[nb][0] - m0);
            float e1 = __expf(c[nb][1] - m0);
            float e2 = __expf(c[nb][2] - m1);
            float e3 = __expf(c[nb][3] - m1);
            s0 += e0 + e1;
            s1 += e2 + e3;
            __half2 lo = __floats2half2_rn(e0, e1);   // rows row0, cols nb*8+2ql..
            __half2 hi = __floats2half2_rn(e2, e3);   // rows row1
            p[nb] = h2_as_u(lo);
            c[nb][2] = __uint_as_float(h2_as_u(hi));  // stash hi in dead slot
        }
        s0 += __shfl_xor_sync(~0u, s0, 1);
        s0 += __shfl_xor_sync(~0u, s0, 2);
        s1 += __shfl_xor_sync(~0u, s1, 1);
        s1 += __shfl_xor_sync(~0u, s1, 2);
        float rinv0 = 1.0f / s0, rinv1 = 1.0f / s1;

        // ---- O = P V ----
        float o[8][4];
#pragma unroll
        for (int d = 0; d < 8; d++)
#pragma unroll
            for (int j = 0; j < 4; j++) o[d][j] = 0.0f;

        const int lkv = ((lane >> 3) & 1) * 8 + (lane & 7); // k row within 16
        const int ldv = (lane >> 4) * 8;                    // d col offset
#pragma unroll
        for (int kc = 0; kc < 13; kc++) {
            unsigned pa[4];
            pa[0] = p[2 * kc];                                    // rows row0, k 0..7
            pa[1] = __float_as_uint(c[2 * kc][2]);                // rows row1, k 0..7
            if (kc < 12) {
                pa[2] = p[2 * kc + 1];                            // rows row0, k 8..15
                pa[3] = __float_as_uint(c[2 * kc + 1][2]);        // rows row1, k 8..15
            } else {
                pa[2] = 0; pa[3] = 0;
            }
#pragma unroll
            for (int dp = 0; dp < 4; dp++) {
                unsigned b0, b1, b2, b3;
                ldsm4t(b0, b1, b2, b3, Vsm + (kc * 16 + lkv) * 72 + dp * 16 + ldv);
                mma16816(o[2 * dp], pa, b0, b1);
                mma16816(o[2 * dp + 1], pa, b2, b3);
            }
        }

        // ---- write normalized output ----
        if (row0 < NN) {
            __half2* op = reinterpret_cast<__half2*>(
                g_AO + (size_t)(b * NN + row0) * DIM + h * DH);
#pragma unroll
            for (int d = 0; d < 8; d++)
                op[d * 4 + ql] = __floats2half2_rn(o[d][0] * rinv0, o[d][1] * rinv0);
        }
        if (row1 < NN) {
            __half2* op = reinterpret_cast<__half2*>(
                g_AO + (size_t)(b * NN + row1) * DIM + h * DH);
#pragma unroll
            for (int d = 0; d < 8; d++)
                op[d * 4 + ql] = __floats2half2_rn(o[d][2] * rinv1, o[d][3] * rinv1);
        }
    }
}

// ---------------- launch ----------------
extern "C" void kernel_launch(void* const* d_in, const int* in_sizes, int n_in,
                              void* d_out, int out_size) {
    const float* x     = (const float*)d_in[0];
    const float* qkvw  = (const float*)d_in[1];
    const float* projw = (const float*)d_in[2];
    const float* projb = (const float*)d_in[3];
    const float* btab  = (const float*)d_in[4];
    const int*   ridx  = (const int*)d_in[5];
    float* out = (float*)d_out;

    cudaFuncSetAttribute(attn_kernel, cudaFuncAttributeMaxDynamicSharedMemorySize,
                         SMEM_ATTN);

    const int ncv = NX2 + NW12 + NW22;
    f2h_all<<<(ncv + 255) / 256, 256>>>(x, qkvw, projw);           // 0

    const int nb = HH * NPR * NP;
    bias_kernel<<<(nb + 255) / 256, 256>>>(btab, ridx);            // 1

    gemm_kernel<<<dim3(3 * DIM / 128, MTOT / 128), 256>>>(0, nullptr, nullptr); // 2

    attn_kernel<<<BB * HH, 256, SMEM_ATTN>>>();                    // 3 (profiled)

    gemm_kernel<<<dim3(DIM / 128, MTOT / 128), 256>>>(1, projb, out); // 4
}

// round 8
// speedup vs baseline: 2.2192x; 1.1325x over previous
#include <cuda_runtime.h>
#include <cuda_fp16.h>
#include <mma.h>

using namespace nvcuda;

// Problem constants
#define BB   128
#define NN   197
#define HH   12
#define DH   64
#define DIM  768
#define MTOT (BB * NN)          // 25216
#define TABLE 730
#define NP   208                // padded cols for bias / S
#define NPR  256                // padded rows for bias

// ---------------- scratch (device globals; no allocations allowed) ----------
__device__ alignas(16) __half g_Xh[(size_t)MTOT * DIM];
__device__ alignas(16) __half g_Wqkv[(size_t)3 * DIM * DIM];
__device__ alignas(16) __half g_Wp[(size_t)DIM * DIM];
__device__ alignas(16) __half g_Q[(size_t)BB * HH * NN * DH];
__device__ alignas(16) __half g_K[(size_t)BB * HH * NN * DH];
__device__ alignas(16) __half g_V[(size_t)BB * HH * NN * DH];
__device__ alignas(16) __half g_AO[(size_t)MTOT * DIM];
__device__ alignas(16) float  g_bias[(size_t)HH * NPR * NP];

// ---------------- cp.async helpers ----------------
__device__ __forceinline__ void cpa16(void* dst, const void* src) {
    unsigned sa = (unsigned)__cvta_generic_to_shared(dst);
    asm volatile("cp.async.cg.shared.global [%0], [%1], 16;" :: "r"(sa), "l"(src));
}
#define CP_COMMIT() asm volatile("cp.async.commit_group;")
#define CP_WAIT(n)  asm volatile("cp.async.wait_group %0;" :: "n"(n))

// ---------------- bit-cast helpers ----------------
__device__ __forceinline__ unsigned h2_as_u(__half2 h) {
    return *reinterpret_cast<unsigned*>(&h);
}

// ---------------- mma / ldmatrix helpers ----------------
__device__ __forceinline__ void ldsm4(unsigned& r0, unsigned& r1, unsigned& r2,
                                      unsigned& r3, const void* p) {
    unsigned a = (unsigned)__cvta_generic_to_shared(p);
    asm volatile("ldmatrix.sync.aligned.m8n8.x4.shared.b16 {%0,%1,%2,%3}, [%4];"
                 : "=r"(r0), "=r"(r1), "=r"(r2), "=r"(r3) : "r"(a));
}
__device__ __forceinline__ void ldsm4t(unsigned& r0, unsigned& r1, unsigned& r2,
                                       unsigned& r3, const void* p) {
    unsigned a = (unsigned)__cvta_generic_to_shared(p);
    asm volatile("ldmatrix.sync.aligned.m8n8.x4.trans.shared.b16 {%0,%1,%2,%3}, [%4];"
                 : "=r"(r0), "=r"(r1), "=r"(r2), "=r"(r3) : "r"(a));
}
__device__ __forceinline__ void mma16816(float* c, const unsigned* a,
                                         unsigned b0, unsigned b1) {
    asm volatile(
        "mma.sync.aligned.m16n8k16.row.col.f32.f16.f16.f32 "
        "{%0,%1,%2,%3}, {%4,%5,%6,%7}, {%8,%9}, {%0,%1,%2,%3};"
        : "+f"(c[0]), "+f"(c[1]), "+f"(c[2]), "+f"(c[3])
        : "r"(a[0]), "r"(a[1]), "r"(a[2]), "r"(a[3]), "r"(b0), "r"(b1));
}

// ---------------- fp32 -> fp16 converts (split for profiling slots) ---------
#define NX2  (MTOT * DIM / 2)
#define NW12 (3 * DIM * DIM / 2)
#define NW22 (DIM * DIM / 2)
__global__ void f2h_x(const float* __restrict__ x) {
    int i = blockIdx.x * blockDim.x + threadIdx.x;
    if (i < NX2) {
        float2 v = reinterpret_cast<const float2*>(x)[i];
        reinterpret_cast<__half2*>(g_Xh)[i] = __floats2half2_rn(v.x, v.y);
    }
}
__global__ void f2h_w(const float* __restrict__ qkvw, const float* __restrict__ projw) {
    int i = blockIdx.x * blockDim.x + threadIdx.x;
    if (i < NW12) {
        float2 v = reinterpret_cast<const float2*>(qkvw)[i];
        reinterpret_cast<__half2*>(g_Wqkv)[i] = __floats2half2_rn(v.x, v.y);
    } else if (i < NW12 + NW22) {
        int j = i - NW12;
        float2 v = reinterpret_cast<const float2*>(projw)[j];
        reinterpret_cast<__half2*>(g_Wp)[j] = __floats2half2_rn(v.x, v.y);
    }
}

// ---------------- expand bias into padded [12,256,208] fp32 ------------------
__global__ void bias_kernel(const float* __restrict__ tab, const int* __restrict__ ridx) {
    int idx = blockIdx.x * blockDim.x + threadIdx.x;
    const int TOT = HH * NPR * NP;
    if (idx >= TOT) return;
    int h = idx / (NPR * NP);
    int rem = idx - h * (NPR * NP);
    int r = rem / NP, c = rem - r * NP;
    float v = 0.0f;
    if (r < NN && c < NN) v = tab[ridx[r * NN + c] * HH + h];
    g_bias[idx] = v;
}

// ---------------- WMMA GEMM: GBK=64, 3-stage, dynamic smem -------------------
#define GBK 64
#define GNT (DIM / GBK)        // 12 k-steps
#define GSTG 3
#define GSTRIDE 72             // 64 + 8 pad halves
#define STAGE_BYTES (2 * 128 * GSTRIDE * 2)   // A + B per stage = 36864
#define SMEM_GEMM (GSTG * STAGE_BYTES)        // 110592

__global__ __launch_bounds__(256, 2)
void gemm_kernel(int mode, const float* __restrict__ bias, float* __restrict__ outf) {
    extern __shared__ __align__(16) char smraw[];
    __half* AsP[GSTG];
    __half* BsP[GSTG];
#pragma unroll
    for (int s = 0; s < GSTG; s++) {
        AsP[s] = reinterpret_cast<__half*>(smraw + s * STAGE_BYTES);
        BsP[s] = reinterpret_cast<__half*>(smraw + s * STAGE_BYTES + 128 * GSTRIDE * 2);
    }
    float (*Cs)[72] = reinterpret_cast<float(*)[72]>(smraw);   // epilogue overlay

    const __half* A = (mode == 0) ? g_Xh : g_AO;
    const __half* W = (mode == 0) ? g_Wqkv : g_Wp;

    const int m0 = blockIdx.y * 128;
    const int n0 = blockIdx.x * 128;
    const int tid = threadIdx.x;
    const int wid = tid >> 5;
    const int wm = wid >> 2, wn = wid & 3;   // 2 x 4; warp owns 64x32

    wmma::fragment<wmma::accumulator, 16, 16, 16, float> acc[4][2];
#pragma unroll
    for (int i = 0; i < 4; i++)
#pragma unroll
        for (int j = 0; j < 2; j++) wmma::fill_fragment(acc[i][j], 0.0f);

    auto prefetch = [&](int kt, int s) {
        const __half* Ab = A + (size_t)m0 * DIM + kt * GBK;
        const __half* Bb = W + (size_t)n0 * DIM + kt * GBK;
#pragma unroll
        for (int t = tid; t < 1024; t += 256) {
            int r = t >> 3, c = t & 7;
            cpa16(AsP[s] + r * GSTRIDE + c * 8, Ab + (size_t)r * DIM + c * 8);
        }
#pragma unroll
        for (int t = tid; t < 1024; t += 256) {
            int r = t >> 3, c = t & 7;
            cpa16(BsP[s] + r * GSTRIDE + c * 8, Bb + (size_t)r * DIM + c * 8);
        }
    };

    prefetch(0, 0);
    CP_COMMIT();
    prefetch(1, 1);
    CP_COMMIT();

    for (int kt = 0; kt < GNT; kt++) {
        const int s = kt % GSTG;
        CP_WAIT(1);
        __syncthreads();
        if (kt + 2 < GNT) {
            prefetch(kt + 2, (kt + 2) % GSTG);
            CP_COMMIT();
        }
#pragma unroll
        for (int kk = 0; kk < GBK; kk += 16) {
            wmma::fragment<wmma::matrix_a, 16, 16, 16, __half, wmma::row_major> af[4];
            wmma::fragment<wmma::matrix_b, 16, 16, 16, __half, wmma::col_major> bf[2];
#pragma unroll
            for (int i = 0; i < 4; i++)
                wmma::load_matrix_sync(af[i],
                    AsP[s] + (wm * 64 + i * 16) * GSTRIDE + kk, GSTRIDE);
#pragma unroll
            for (int j = 0; j < 2; j++)
                wmma::load_matrix_sync(bf[j],
                    BsP[s] + (wn * 32 + j * 16) * GSTRIDE + kk, GSTRIDE);
#pragma unroll
            for (int i = 0; i < 4; i++)
#pragma unroll
                for (int j = 0; j < 2; j++)
                    wmma::mma_sync(acc[i][j], af[i], bf[j], acc[i][j]);
        }
    }
    __syncthreads();

#pragma unroll
    for (int half = 0; half < 2; half++) {
        if ((wn >> 1) == half) {
#pragma unroll
            for (int i = 0; i < 4; i++)
#pragma unroll
                for (int j = 0; j < 2; j++)
                    wmma::store_matrix_sync(&Cs[wm * 64 + i * 16][(wn & 1) * 32 + j * 16],
                                            acc[i][j], 72, wmma::mem_row_major);
        }
        __syncthreads();
        if (mode == 1) {
            for (int idx = tid; idx < 128 * 64; idx += 256) {
                int r = idx >> 6, c = idx & 63;
                int m = m0 + r, n = n0 + half * 64 + c;
                outf[(size_t)m * DIM + n] = Cs[r][c] + bias[n];
            }
        } else {
            for (int idx = tid; idx < 128 * 64; idx += 256) {
                int r = idx >> 6, c = idx & 63;
                int m = m0 + r, n = n0 + half * 64 + c;
                float v = Cs[r][c];
                int which = n / DIM;
                int rem = n - which * DIM;
                int h = rem >> 6, d = rem & 63;
                int b = m / NN, t = m - b * NN;
                size_t off = ((size_t)(b * HH + h) * NN + t) * DH + d;
                if (which == 0)      g_Q[off] = __float2half(v * 0.125f);
                else if (which == 1) g_K[off] = __float2half(v);
                else                 g_V[off] = __float2half(v);
            }
        }
        __syncthreads();
    }
}

// ---------------- FA2-style attention (unchanged from R7) --------------------
#define SMEM_ATTN (2 * NP * 72 * 2)

__global__ __launch_bounds__(256)
void attn_kernel() {
    extern __shared__ __align__(16) char sm[];
    __half* Ksm = reinterpret_cast<__half*>(sm);
    __half* Vsm = reinterpret_cast<__half*>(sm + NP * 72 * 2);

    const int bh = blockIdx.x;
    const int b = bh / HH, h = bh - b * HH;
    const __half* Kg = g_K + (size_t)bh * NN * DH;
    const __half* Vg = g_V + (size_t)bh * NN * DH;
    const __half* Qg = g_Q + (size_t)bh * NN * DH;
    const float* biasH = g_bias + (size_t)h * NPR * NP;
    const int tid = threadIdx.x, lane = tid & 31, wid = tid >> 5;

    for (int idx = tid; idx < NP * 8; idx += 256) {
        int r = idx >> 3, c = idx & 7;
        uint4 z = make_uint4(0, 0, 0, 0);
        uint4 kv = (r < NN) ? *reinterpret_cast<const uint4*>(&Kg[r * DH + c * 8]) : z;
        uint4 vv = (r < NN) ? *reinterpret_cast<const uint4*>(&Vg[r * DH + c * 8]) : z;
        *reinterpret_cast<uint4*>(&Ksm[r * 72 + c * 8]) = kv;
        *reinterpret_cast<uint4*>(&Vsm[r * 72 + c * 8]) = vv;
    }
    __syncthreads();

    const int qd = lane >> 2;
    const int ql = lane & 3;

    for (int strip = wid; strip < 13; strip += 8) {
        const int r0 = strip * 16;
        const int row0 = r0 + qd;
        const int row1 = row0 + 8;

        unsigned a[4][4];
        {
            const __half2* Qa = reinterpret_cast<const __half2*>(
                Qg + (size_t)min(row0, NN - 1) * DH);
            const __half2* Qb = reinterpret_cast<const __half2*>(
                Qg + (size_t)min(row1, NN - 1) * DH);
#pragma unroll
            for (int kk = 0; kk < 4; kk++) {
                a[kk][0] = reinterpret_cast<const unsigned*>(Qa)[kk * 8 + ql];
                a[kk][1] = reinterpret_cast<const unsigned*>(Qb)[kk * 8 + ql];
                a[kk][2] = reinterpret_cast<const unsigned*>(Qa)[kk * 8 + 4 + ql];
                a[kk][3] = reinterpret_cast<const unsigned*>(Qb)[kk * 8 + 4 + ql];
            }
        }

        float c[25][4];
#pragma unroll
        for (int nb = 0; nb < 25; nb++) {
            float2 b0 = *reinterpret_cast<const float2*>(
                biasH + (size_t)row0 * NP + nb * 8 + ql * 2);
            float2 b1 = *reinterpret_cast<const float2*>(
                biasH + (size_t)row1 * NP + nb * 8 + ql * 2);
            c[nb][0] = b0.x; c[nb][1] = b0.y; c[nb][2] = b1.x; c[nb][3] = b1.y;
        }

        const int ln = (lane >> 4) * 8 + (lane & 7);
        const int lk = ((lane >> 3) & 1) * 8;
#pragma unroll
        for (int np = 0; np < 13; np++) {
#pragma unroll
            for (int kk = 0; kk < 4; kk++) {
                unsigned b0, b1, b2, b3;
                ldsm4(b0, b1, b2, b3, Ksm + (np * 16 + ln) * 72 + kk * 16 + lk);
                mma16816(c[2 * np], a[kk], b0, b1);
                if (np < 12) mma16816(c[2 * np + 1], a[kk], b2, b3);
            }
        }

        {
            int c0 = 192 + ql * 2;
            if (c0 >= NN)     { c[24][0] = -1e30f; c[24][2] = -1e30f; }
            if (c0 + 1 >= NN) { c[24][1] = -1e30f; c[24][3] = -1e30f; }
        }

        float m0 = -1e30f, m1 = -1e30f;
#pragma unroll
        for (int nb = 0; nb < 25; nb++) {
            m0 = fmaxf(m0, fmaxf(c[nb][0], c[nb][1]));
            m1 = fmaxf(m1, fmaxf(c[nb][2], c[nb][3]));
        }
        m0 = fmaxf(m0, __shfl_xor_sync(~0u, m0, 1));
        m0 = fmaxf(m0, __shfl_xor_sync(~0u, m0, 2));
        m1 = fmaxf(m1, __shfl_xor_sync(~0u, m1, 1));
        m1 = fmaxf(m1, __shfl_xor_sync(~0u, m1, 2));

        float s0 = 0.0f, s1 = 0.0f;
        unsigned p[25];
#pragma unroll
        for (int nb = 0; nb < 25; nb++) {
            float e0 = __expf(c[nb][0] - m0);
            float e1 = __expf(c[nb][1] - m0);
            float e2 = __expf(c[nb][2] - m1);
            float e3 = __expf(c[nb][3] - m1);
            s0 += e0 + e1;
            s1 += e2 + e3;
            __half2 lo = __floats2half2_rn(e0, e1);
            __half2 hi = __floats2half2_rn(e2, e3);
            p[nb] = h2_as_u(lo);
            c[nb][2] = __uint_as_float(h2_as_u(hi));
        }
        s0 += __shfl_xor_sync(~0u, s0, 1);
        s0 += __shfl_xor_sync(~0u, s0, 2);
        s1 += __shfl_xor_sync(~0u, s1, 1);
        s1 += __shfl_xor_sync(~0u, s1, 2);
        float rinv0 = 1.0f / s0, rinv1 = 1.0f / s1;

        float o[8][4];
#pragma unroll
        for (int d = 0; d < 8; d++)
#pragma unroll
            for (int j = 0; j < 4; j++) o[d][j] = 0.0f;

        const int lkv = ((lane >> 3) & 1) * 8 + (lane & 7);
        const int ldv = (lane >> 4) * 8;
#pragma unroll
        for (int kc = 0; kc < 13; kc++) {
            unsigned pa[4];
            pa[0] = p[2 * kc];
            pa[1] = __float_as_uint(c[2 * kc][2]);
            if (kc < 12) {
                pa[2] = p[2 * kc + 1];
                pa[3] = __float_as_uint(c[2 * kc + 1][2]);
            } else {
                pa[2] = 0; pa[3] = 0;
            }
#pragma unroll
            for (int dp = 0; dp < 4; dp++) {
                unsigned b0, b1, b2, b3;
                ldsm4t(b0, b1, b2, b3, Vsm + (kc * 16 + lkv) * 72 + dp * 16 + ldv);
                mma16816(o[2 * dp], pa, b0, b1);
                mma16816(o[2 * dp + 1], pa, b2, b3);
            }
        }

        if (row0 < NN) {
            __half2* op = reinterpret_cast<__half2*>(
                g_AO + (size_t)(b * NN + row0) * DIM + h * DH);
#pragma unroll
            for (int d = 0; d < 8; d++)
                op[d * 4 + ql] = __floats2half2_rn(o[d][0] * rinv0, o[d][1] * rinv0);
        }
        if (row1 < NN) {
            __half2* op = reinterpret_cast<__half2*>(
                g_AO + (size_t)(b * NN + row1) * DIM + h * DH);
#pragma unroll
            for (int d = 0; d < 8; d++)
                op[d * 4 + ql] = __floats2half2_rn(o[d][2] * rinv1, o[d][3] * rinv1);
        }
    }
}

// ---------------- launch ----------------
extern "C" void kernel_launch(void* const* d_in, const int* in_sizes, int n_in,
                              void* d_out, int out_size) {
    const float* x     = (const float*)d_in[0];
    const float* qkvw  = (const float*)d_in[1];
    const float* projw = (const float*)d_in[2];
    const float* projb = (const float*)d_in[3];
    const float* btab  = (const float*)d_in[4];
    const int*   ridx  = (const int*)d_in[5];
    float* out = (float*)d_out;

    cudaFuncSetAttribute(attn_kernel, cudaFuncAttributeMaxDynamicSharedMemorySize,
                         SMEM_ATTN);
    cudaFuncSetAttribute(gemm_kernel, cudaFuncAttributeMaxDynamicSharedMemorySize,
                         SMEM_GEMM);

    f2h_x<<<(NX2 + 255) / 256, 256>>>(x);                           // 0
    f2h_w<<<(NW12 + NW22 + 255) / 256, 256>>>(qkvw, projw);         // 1

    const int nb = HH * NPR * NP;
    bias_kernel<<<(nb + 255) / 256, 256>>>(btab, ridx);             // 2

    // QKV: M=25216, N=2304                                          // 3 (profiled)
    gemm_kernel<<<dim3(3 * DIM / 128, MTOT / 128), 256, SMEM_GEMM>>>(0, nullptr, nullptr);

    attn_kernel<<<BB * HH, 256, SMEM_ATTN>>>();                     // 4

    gemm_kernel<<<dim3(DIM / 128, MTOT / 128), 256, SMEM_GEMM>>>(1, projb, out); // 5
}

// round 10
// speedup vs baseline: 2.7033x; 1.2181x over previous
#include <cuda_runtime.h>
#include <cuda_fp16.h>
#include <cstdint>

// Problem constants
#define BB   128
#define HH   12
#define DH   64
#define DIM  768
#define NN   197
#define MTOT (BB * NN)          // 25216 = 197 * 128
#define TABLE 730
#define NP   208                // padded cols for bias / S
#define NPR  256                // padded rows for bias

// ---------------- scratch (device globals; no allocations allowed) ----------
__device__ alignas(16) __half g_Xh[(size_t)MTOT * DIM];
__device__ alignas(16) __half g_Wqkv[(size_t)3 * DIM * DIM];
__device__ alignas(16) __half g_Wp[(size_t)DIM * DIM];
__device__ alignas(16) __half g_Q[(size_t)BB * HH * NN * DH];
__device__ alignas(16) __half g_K[(size_t)BB * HH * NN * DH];
__device__ alignas(16) __half g_V[(size_t)BB * HH * NN * DH];
__device__ alignas(16) __half g_AO[(size_t)MTOT * DIM];
__device__ alignas(16) float  g_bias[(size_t)HH * NPR * NP];

// ---------------- helpers ----------------
__device__ __forceinline__ unsigned smem_u32(const void* p) {
    return (unsigned)__cvta_generic_to_shared(p);
}
__device__ __forceinline__ unsigned h2_as_u(__half2 h) {
    return *reinterpret_cast<unsigned*>(&h);
}
__device__ __forceinline__ void cpa16s(unsigned sdst, const void* src) {
    asm volatile("cp.async.cg.shared.global [%0], [%1], 16;" :: "r"(sdst), "l"(src));
}
#define CP_COMMIT() asm volatile("cp.async.commit_group;")
#define CP_WAIT(n)  asm volatile("cp.async.wait_group %0;" :: "n"(n))

__device__ __forceinline__ void ldsm4(unsigned& r0, unsigned& r1, unsigned& r2,
                                      unsigned& r3, unsigned a) {
    asm volatile("ldmatrix.sync.aligned.m8n8.x4.shared.b16 {%0,%1,%2,%3}, [%4];"
                 : "=r"(r0), "=r"(r1), "=r"(r2), "=r"(r3) : "r"(a));
}
__device__ __forceinline__ void ldsm4p(unsigned& r0, unsigned& r1, unsigned& r2,
                                       unsigned& r3, const void* p) {
    ldsm4(r0, r1, r2, r3, smem_u32(p));
}
__device__ __forceinline__ void ldsm4t(unsigned& r0, unsigned& r1, unsigned& r2,
                                       unsigned& r3, const void* p) {
    unsigned a = smem_u32(p);
    asm volatile("ldmatrix.sync.aligned.m8n8.x4.trans.shared.b16 {%0,%1,%2,%3}, [%4];"
                 : "=r"(r0), "=r"(r1), "=r"(r2), "=r"(r3) : "r"(a));
}
__device__ __forceinline__ void mma16816(float* c, const unsigned* a,
                                         unsigned b0, unsigned b1) {
    asm volatile(
        "mma.sync.aligned.m16n8k16.row.col.f32.f16.f16.f32 "
        "{%0,%1,%2,%3}, {%4,%5,%6,%7}, {%8,%9}, {%0,%1,%2,%3};"
        : "+f"(c[0]), "+f"(c[1]), "+f"(c[2]), "+f"(c[3])
        : "r"(a[0]), "r"(a[1]), "r"(a[2]), "r"(a[3]), "r"(b0), "r"(b1));
}

// ---------------- fp32 -> fp16 converts ----------------
#define NX2  (MTOT * DIM / 2)
#define NW12 (3 * DIM * DIM / 2)
#define NW22 (DIM * DIM / 2)
__global__ void f2h_x(const float* __restrict__ x) {
    int i = blockIdx.x * blockDim.x + threadIdx.x;
    if (i < NX2) {
        float2 v = reinterpret_cast<const float2*>(x)[i];
        reinterpret_cast<__half2*>(g_Xh)[i] = __floats2half2_rn(v.x, v.y);
    }
}
__global__ void f2h_w(const float* __restrict__ qkvw, const float* __restrict__ projw) {
    int i = blockIdx.x * blockDim.x + threadIdx.x;
    if (i < NW12) {
        float2 v = reinterpret_cast<const float2*>(qkvw)[i];
        reinterpret_cast<__half2*>(g_Wqkv)[i] = __floats2half2_rn(v.x, v.y);
    } else if (i < NW12 + NW22) {
        int j = i - NW12;
        float2 v = reinterpret_cast<const float2*>(projw)[j];
        reinterpret_cast<__half2*>(g_Wp)[j] = __floats2half2_rn(v.x, v.y);
    }
}

// ---------------- expand bias into padded [12,256,208] fp32 ------------------
__global__ void bias_kernel(const float* __restrict__ tab, const int* __restrict__ ridx) {
    int idx = blockIdx.x * blockDim.x + threadIdx.x;
    const int TOT = HH * NPR * NP;
    if (idx >= TOT) return;
    int h = idx / (NPR * NP);
    int rem = idx - h * (NPR * NP);
    int r = rem / NP, c = rem - r * NP;
    float v = 0.0f;
    if (r < NN && c < NN) v = tab[ridx[r * NN + c] * HH + h];
    g_bias[idx] = v;
}

// ---------------- raw-mma GEMM: 128x128 tile, 4 warps x (64x64) --------------
#define GBK 64
#define NKCH (DIM / GBK)      // 12 chunks
#define GSTG 3
#define GST 72                // row stride in halves
#define OPB (128 * GST * 2)   // 18432 bytes per operand per stage
#define STB (2 * OPB)         // 36864
#define SMEM_G (GSTG * STB)   // 110592

__global__ __launch_bounds__(128, 2)
void gemm_kernel(int mode, const float* __restrict__ bias, float* __restrict__ outf) {
    extern __shared__ __align__(16) char smraw[];

    const __half* A = (mode == 0) ? g_Xh : g_AO;
    const __half* W = (mode == 0) ? g_Wqkv : g_Wp;
    const int m0 = blockIdx.y * 128;
    const int n0 = blockIdx.x * 128;
    const int tid = threadIdx.x, lane = tid & 31, wid = tid >> 5;
    const int wm = wid >> 1, wn = wid & 1;   // 2x2 warps, each 64x64

    const unsigned sbase = smem_u32(smraw);
    auto stA = [&](int s) { return sbase + s * STB; };
    auto stB = [&](int s) { return sbase + s * STB + OPB; };

    float c[4][8][4];
#pragma unroll
    for (int mi = 0; mi < 4; mi++)
#pragma unroll
        for (int ni = 0; ni < 8; ni++)
#pragma unroll
            for (int j = 0; j < 4; j++) c[mi][ni][j] = 0.0f;

    auto prefetch = [&](int kt, int s) {
        const __half* Ab = A + (size_t)m0 * DIM + kt * GBK;
        const __half* Bb = W + (size_t)n0 * DIM + kt * GBK;
        unsigned sa = stA(s), sb = stB(s);
#pragma unroll
        for (int t = tid; t < 1024; t += 128) {
            int r = t >> 3, u = t & 7;
            cpa16s(sa + (r * GST + u * 8) * 2, Ab + (size_t)r * DIM + u * 8);
        }
#pragma unroll
        for (int t = tid; t < 1024; t += 128) {
            int r = t >> 3, u = t & 7;
            cpa16s(sb + (r * GST + u * 8) * 2, Bb + (size_t)r * DIM + u * 8);
        }
    };

    prefetch(0, 0); CP_COMMIT();
    prefetch(1, 1); CP_COMMIT();

    // ldmatrix lane addressing
    const int la_r = lane & 15, la_k = (lane >> 4) * 8;              // A frags
    const int lb_n = (lane >> 4) * 8 + (lane & 7);                   // B frags
    const int lb_k = ((lane >> 3) & 1) * 8;

    for (int kt = 0; kt < NKCH; kt++) {
        const int s = kt % GSTG;
        if (kt == NKCH - 1) { CP_WAIT(0); } else { CP_WAIT(1); }
        __syncthreads();
        if (kt + 2 < NKCH) {
            prefetch(kt + 2, (kt + 2) % GSTG);
            CP_COMMIT();
        }
        const unsigned sa = stA(s), sb = stB(s);
#pragma unroll
        for (int kk = 0; kk < 4; kk++) {
            unsigned am[4][4];
#pragma unroll
            for (int mi = 0; mi < 4; mi++)
                ldsm4(am[mi][0], am[mi][1], am[mi][2], am[mi][3],
                      sa + ((wm * 64 + mi * 16 + la_r) * GST + kk * 16 + la_k) * 2);
#pragma unroll
            for (int nt = 0; nt < 4; nt++) {
                unsigned b0, b1, b2, b3;
                ldsm4(b0, b1, b2, b3,
                      sb + ((wn * 64 + nt * 16 + lb_n) * GST + kk * 16 + lb_k) * 2);
#pragma unroll
                for (int mi = 0; mi < 4; mi++) {
                    mma16816(c[mi][2 * nt],     am[mi], b0, b1);
                    mma16816(c[mi][2 * nt + 1], am[mi], b2, b3);
                }
            }
        }
    }

    // ---- register-direct epilogue ----
    const int qd = lane >> 2, ql = lane & 3;
    const int nbase = n0 + wn * 64;
    if (mode == 1) {
#pragma unroll
        for (int mi = 0; mi < 4; mi++) {
            int mr0 = m0 + wm * 64 + mi * 16 + qd;
            float* d0 = outf + (size_t)mr0 * DIM + nbase;
            float* d1 = d0 + 8 * DIM;
#pragma unroll
            for (int ni = 0; ni < 8; ni++) {
                int col = ni * 8 + ql * 2;
                float2 bv = *reinterpret_cast<const float2*>(bias + nbase + col);
                float2 lo = make_float2(c[mi][ni][0] + bv.x, c[mi][ni][1] + bv.y);
                float2 hi = make_float2(c[mi][ni][2] + bv.x, c[mi][ni][3] + bv.y);
                *reinterpret_cast<float2*>(d0 + col) = lo;
                *reinterpret_cast<float2*>(d1 + col) = hi;
            }
        }
    } else {
        const int which = nbase / DIM;
        const int rem = nbase - which * DIM;
        const int h = rem >> 6;                    // 64-aligned head
        __half* dstB = (which == 0) ? g_Q : (which == 1) ? g_K : g_V;
        const float scl = (which == 0) ? 0.125f : 1.0f;
#pragma unroll
        for (int mi = 0; mi < 4; mi++) {
            int mr0 = m0 + wm * 64 + mi * 16 + qd;
            int mr1 = mr0 + 8;
            int b0r = mr0 / NN, t0 = mr0 - b0r * NN;
            int b1r = mr1 / NN, t1 = mr1 - b1r * NN;
            __half* p0 = dstB + ((size_t)(b0r * HH + h) * NN + t0) * DH;
            __half* p1 = dstB + ((size_t)(b1r * HH + h) * NN + t1) * DH;
#pragma unroll
            for (int ni = 0; ni < 8; ni++) {
                int d = ni * 8 + ql * 2;
                *reinterpret_cast<__half2*>(p0 + d) =
                    __floats2half2_rn(c[mi][ni][0] * scl, c[mi][ni][1] * scl);
                *reinterpret_cast<__half2*>(p1 + d) =
                    __floats2half2_rn(c[mi][ni][2] * scl, c[mi][ni][3] * scl);
            }
        }
    }
}

// ---------------- FA2-style attention (unchanged from R7/R8) -----------------
#define SMEM_ATTN (2 * NP * 72 * 2)

__global__ __launch_bounds__(256)
void attn_kernel() {
    extern __shared__ __align__(16) char sm[];
    __half* Ksm = reinterpret_cast<__half*>(sm);
    __half* Vsm = reinterpret_cast<__half*>(sm + NP * 72 * 2);

    const int bh = blockIdx.x;
    const int b = bh / HH, h = bh - b * HH;
    const __half* Kg = g_K + (size_t)bh * NN * DH;
    const __half* Vg = g_V + (size_t)bh * NN * DH;
    const __half* Qg = g_Q + (size_t)bh * NN * DH;
    const float* biasH = g_bias + (size_t)h * NPR * NP;
    const int tid = threadIdx.x, lane = tid & 31, wid = tid >> 5;

    for (int idx = tid; idx < NP * 8; idx += 256) {
        int r = idx >> 3, c = idx & 7;
        uint4 z = make_uint4(0, 0, 0, 0);
        uint4 kv = (r < NN) ? *reinterpret_cast<const uint4*>(&Kg[r * DH + c * 8]) : z;
        uint4 vv = (r < NN) ? *reinterpret_cast<const uint4*>(&Vg[r * DH + c * 8]) : z;
        *reinterpret_cast<uint4*>(&Ksm[r * 72 + c * 8]) = kv;
        *reinterpret_cast<uint4*>(&Vsm[r * 72 + c * 8]) = vv;
    }
    __syncthreads();

    const int qd = lane >> 2;
    const int ql = lane & 3;

    for (int strip = wid; strip < 13; strip += 8) {
        const int r0 = strip * 16;
        const int row0 = r0 + qd;
        const int row1 = row0 + 8;

        unsigned a[4][4];
        {
            const __half2* Qa = reinterpret_cast<const __half2*>(
                Qg + (size_t)min(row0, NN - 1) * DH);
            const __half2* Qb = reinterpret_cast<const __half2*>(
                Qg + (size_t)min(row1, NN - 1) * DH);
#pragma unroll
            for (int kk = 0; kk < 4; kk++) {
                a[kk][0] = reinterpret_cast<const unsigned*>(Qa)[kk * 8 + ql];
                a[kk][1] = reinterpret_cast<const unsigned*>(Qb)[kk * 8 + ql];
                a[kk][2] = reinterpret_cast<const unsigned*>(Qa)[kk * 8 + 4 + ql];
                a[kk][3] = reinterpret_cast<const unsigned*>(Qb)[kk * 8 + 4 + ql];
            }
        }

        float c[25][4];
#pragma unroll
        for (int nb = 0; nb < 25; nb++) {
            float2 b0 = *reinterpret_cast<const float2*>(
                biasH + (size_t)row0 * NP + nb * 8 + ql * 2);
            float2 b1 = *reinterpret_cast<const float2*>(
                biasH + (size_t)row1 * NP + nb * 8 + ql * 2);
            c[nb][0] = b0.x; c[nb][1] = b0.y; c[nb][2] = b1.x; c[nb][3] = b1.y;
        }

        const int ln = (lane >> 4) * 8 + (lane & 7);
        const int lk = ((lane >> 3) & 1) * 8;
#pragma unroll
        for (int np = 0; np < 13; np++) {
#pragma unroll
            for (int kk = 0; kk < 4; kk++) {
                unsigned b0, b1, b2, b3;
                ldsm4p(b0, b1, b2, b3, Ksm + (np * 16 + ln) * 72 + kk * 16 + lk);
                mma16816(c[2 * np], a[kk], b0, b1);
                if (np < 12) mma16816(c[2 * np + 1], a[kk], b2, b3);
            }
        }

        {
            int c0 = 192 + ql * 2;
            if (c0 >= NN)     { c[24][0] = -1e30f; c[24][2] = -1e30f; }
            if (c0 + 1 >= NN) { c[24][1] = -1e30f; c[24][3] = -1e30f; }
        }

        float m0 = -1e30f, m1 = -1e30f;
#pragma unroll
        for (int nb = 0; nb < 25; nb++) {
            m0 = fmaxf(m0, fmaxf(c[nb][0], c[nb][1]));
            m1 = fmaxf(m1, fmaxf(c[nb][2], c[nb][3]));
        }
        m0 = fmaxf(m0, __shfl_xor_sync(~0u, m0, 1));
        m0 = fmaxf(m0, __shfl_xor_sync(~0u, m0, 2));
        m1 = fmaxf(m1, __shfl_xor_sync(~0u, m1, 1));
        m1 = fmaxf(m1, __shfl_xor_sync(~0u, m1, 2));

        float s0 = 0.0f, s1 = 0.0f;
        unsigned p[25];
#pragma unroll
        for (int nb = 0; nb < 25; nb++) {
            float e0 = __expf(c[nb][0] - m0);
            float e1 = __expf(c[nb][1] - m0);
            float e2 = __expf(c[nb][2] - m1);
            float e3 = __expf(c[nb][3] - m1);
            s0 += e0 + e1;
            s1 += e2 + e3;
            __half2 lo = __floats2half2_rn(e0, e1);
            __half2 hi = __floats2half2_rn(e2, e3);
            p[nb] = h2_as_u(lo);
            c[nb][2] = __uint_as_float(h2_as_u(hi));
        }
        s0 += __shfl_xor_sync(~0u, s0, 1);
        s0 += __shfl_xor_sync(~0u, s0, 2);
        s1 += __shfl_xor_sync(~0u, s1, 1);
        s1 += __shfl_xor_sync(~0u, s1, 2);
        float rinv0 = 1.0f / s0, rinv1 = 1.0f / s1;

        float o[8][4];
#pragma unroll
        for (int d = 0; d < 8; d++)
#pragma unroll
            for (int j = 0; j < 4; j++) o[d][j] = 0.0f;

        const int lkv = ((lane >> 3) & 1) * 8 + (lane & 7);
        const int ldv = (lane >> 4) * 8;
#pragma unroll
        for (int kc = 0; kc < 13; kc++) {
            unsigned pa[4];
            pa[0] = p[2 * kc];
            pa[1] = __float_as_uint(c[2 * kc][2]);
            if (kc < 12) {
                pa[2] = p[2 * kc + 1];
                pa[3] = __float_as_uint(c[2 * kc + 1][2]);
            } else {
                pa[2] = 0; pa[3] = 0;
            }
#pragma unroll
            for (int dp = 0; dp < 4; dp++) {
                unsigned b0, b1, b2, b3;
                ldsm4t(b0, b1, b2, b3, Vsm + (kc * 16 + lkv) * 72 + dp * 16 + ldv);
                mma16816(o[2 * dp], pa, b0, b1);
                mma16816(o[2 * dp + 1], pa, b2, b3);
            }
        }

        if (row0 < NN) {
            __half2* op = reinterpret_cast<__half2*>(
                g_AO + (size_t)(b * NN + row0) * DIM + h * DH);
#pragma unroll
            for (int d = 0; d < 8; d++)
                op[d * 4 + ql] = __floats2half2_rn(o[d][0] * rinv0, o[d][1] * rinv0);
        }
        if (row1 < NN) {
            __half2* op = reinterpret_cast<__half2*>(
                g_AO + (size_t)(b * NN + row1) * DIM + h * DH);
#pragma unroll
            for (int d = 0; d < 8; d++)
                op[d * 4 + ql] = __floats2half2_rn(o[d][2] * rinv1, o[d][3] * rinv1);
        }
    }
}

// ---------------- launch ----------------
extern "C" void kernel_launch(void* const* d_in, const int* in_sizes, int n_in,
                              void* d_out, int out_size) {
    const float* x     = (const float*)d_in[0];
    const float* qkvw  = (const float*)d_in[1];
    const float* projw = (const float*)d_in[2];
    const float* projb = (const float*)d_in[3];
    const float* btab  = (const float*)d_in[4];
    const int*   ridx  = (const int*)d_in[5];
    float* out = (float*)d_out;

    cudaFuncSetAttribute(attn_kernel, cudaFuncAttributeMaxDynamicSharedMemorySize,
                         SMEM_ATTN);
    cudaFuncSetAttribute(gemm_kernel, cudaFuncAttributeMaxDynamicSharedMemorySize,
                         SMEM_G);

    f2h_x<<<(NX2 + 255) / 256, 256>>>(x);                            // 0
    f2h_w<<<(NW12 + NW22 + 255) / 256, 256>>>(qkvw, projw);          // 1

    const int nb = HH * NPR * NP;
    bias_kernel<<<(nb + 255) / 256, 256>>>(btab, ridx);              // 2

    // QKV: M=25216 (197 tiles), N=2304 (18 tiles)                    // 3 (profiled)
    gemm_kernel<<<dim3(18, 197), 128, SMEM_G>>>(0, nullptr, nullptr);

    attn_kernel<<<BB * HH, 256, SMEM_ATTN>>>();                      // 4

    // proj: N=768 (6 tiles)                                          // 5
    gemm_kernel<<<dim3(6, 197), 128, SMEM_G>>>(1, projb, out);
}

// round 11
// speedup vs baseline: 2.7053x; 1.0007x over previous
#include <cuda_runtime.h>
#include <cuda_fp16.h>
#include <cstdint>

// Problem constants
#define BB   128
#define HH   12
#define DH   64
#define DIM  768
#define NN   197
#define MTOT (BB * NN)          // 25216 = 197 * 128
#define TABLE 730
#define NP   208                // padded cols for bias / S
#define NPR  256                // padded rows for bias

// ---------------- scratch (device globals; no allocations allowed) ----------
__device__ alignas(16) __half g_Xh[(size_t)MTOT * DIM];
__device__ alignas(16) __half g_Wqkv[(size_t)3 * DIM * DIM];
__device__ alignas(16) __half g_Wp[(size_t)DIM * DIM];
__device__ alignas(16) __half g_Q[(size_t)BB * HH * NN * DH];
__device__ alignas(16) __half g_K[(size_t)BB * HH * NN * DH];
__device__ alignas(16) __half g_V[(size_t)BB * HH * NN * DH];
__device__ alignas(16) __half g_AO[(size_t)MTOT * DIM];
__device__ alignas(16) float  g_bias[(size_t)HH * NPR * NP];

// ---------------- helpers ----------------
__device__ __forceinline__ unsigned smem_u32(const void* p) {
    return (unsigned)__cvta_generic_to_shared(p);
}
__device__ __forceinline__ unsigned h2_as_u(__half2 h) {
    return *reinterpret_cast<unsigned*>(&h);
}
__device__ __forceinline__ void cpa16s(unsigned sdst, const void* src) {
    asm volatile("cp.async.cg.shared.global [%0], [%1], 16;" :: "r"(sdst), "l"(src));
}
#define CP_COMMIT() asm volatile("cp.async.commit_group;")
#define CP_WAIT(n)  asm volatile("cp.async.wait_group %0;" :: "n"(n))

__device__ __forceinline__ void ldsm4(unsigned& r0, unsigned& r1, unsigned& r2,
                                      unsigned& r3, unsigned a) {
    asm volatile("ldmatrix.sync.aligned.m8n8.x4.shared.b16 {%0,%1,%2,%3}, [%4];"
                 : "=r"(r0), "=r"(r1), "=r"(r2), "=r"(r3) : "r"(a));
}
__device__ __forceinline__ void ldsm4p(unsigned& r0, unsigned& r1, unsigned& r2,
                                       unsigned& r3, const void* p) {
    ldsm4(r0, r1, r2, r3, smem_u32(p));
}
__device__ __forceinline__ void ldsm4t(unsigned& r0, unsigned& r1, unsigned& r2,
                                       unsigned& r3, const void* p) {
    unsigned a = smem_u32(p);
    asm volatile("ldmatrix.sync.aligned.m8n8.x4.trans.shared.b16 {%0,%1,%2,%3}, [%4];"
                 : "=r"(r0), "=r"(r1), "=r"(r2), "=r"(r3) : "r"(a));
}
__device__ __forceinline__ void mma16816(float* c, const unsigned* a,
                                         unsigned b0, unsigned b1) {
    asm volatile(
        "mma.sync.aligned.m16n8k16.row.col.f32.f16.f16.f32 "
        "{%0,%1,%2,%3}, {%4,%5,%6,%7}, {%8,%9}, {%0,%1,%2,%3};"
        : "+f"(c[0]), "+f"(c[1]), "+f"(c[2]), "+f"(c[3])
        : "r"(a[0]), "r"(a[1]), "r"(a[2]), "r"(a[3]), "r"(b0), "r"(b1));
}

// ---------------- fp32 -> fp16 converts ----------------
#define NX2  (MTOT * DIM / 2)
#define NW12 (3 * DIM * DIM / 2)
#define NW22 (DIM * DIM / 2)
__global__ void f2h_x(const float* __restrict__ x) {
    int i = blockIdx.x * blockDim.x + threadIdx.x;
    if (i < NX2) {
        float2 v = reinterpret_cast<const float2*>(x)[i];
        reinterpret_cast<__half2*>(g_Xh)[i] = __floats2half2_rn(v.x, v.y);
    }
}
__global__ void f2h_w(const float* __restrict__ qkvw, const float* __restrict__ projw) {
    int i = blockIdx.x * blockDim.x + threadIdx.x;
    if (i < NW12) {
        float2 v = reinterpret_cast<const float2*>(qkvw)[i];
        reinterpret_cast<__half2*>(g_Wqkv)[i] = __floats2half2_rn(v.x, v.y);
    } else if (i < NW12 + NW22) {
        int j = i - NW12;
        float2 v = reinterpret_cast<const float2*>(projw)[j];
        reinterpret_cast<__half2*>(g_Wp)[j] = __floats2half2_rn(v.x, v.y);
    }
}

// ---------------- expand bias into padded [12,256,208] fp32 ------------------
__global__ void bias_kernel(const float* __restrict__ tab, const int* __restrict__ ridx) {
    int idx = blockIdx.x * blockDim.x + threadIdx.x;
    const int TOT = HH * NPR * NP;
    if (idx >= TOT) return;
    int h = idx / (NPR * NP);
    int rem = idx - h * (NPR * NP);
    int r = rem / NP, c = rem - r * NP;
    float v = 0.0f;
    if (r < NN && c < NN) v = tab[ridx[r * NN + c] * HH + h];
    g_bias[idx] = v;
}

// ---------------- raw-mma GEMM: 128x128 tile, 4 warps x (64x64) --------------
#define GBK 64
#define NKCH (DIM / GBK)      // 12 chunks
#define GSTG 3
#define GST 72                // row stride in halves
#define OPB (128 * GST * 2)   // 18432 bytes per operand per stage
#define STB (2 * OPB)         // 36864
#define SMEM_G (GSTG * STB)   // 110592

__global__ __launch_bounds__(128, 2)
void gemm_kernel(int mode, const float* __restrict__ bias, float* __restrict__ outf) {
    extern __shared__ __align__(16) char smraw[];

    const __half* A = (mode == 0) ? g_Xh : g_AO;
    const __half* W = (mode == 0) ? g_Wqkv : g_Wp;
    const int m0 = blockIdx.y * 128;
    const int n0 = blockIdx.x * 128;
    const int tid = threadIdx.x, lane = tid & 31, wid = tid >> 5;
    const int wm = wid >> 1, wn = wid & 1;   // 2x2 warps, each 64x64

    const unsigned sbase = smem_u32(smraw);
    auto stA = [&](int s) { return sbase + s * STB; };
    auto stB = [&](int s) { return sbase + s * STB + OPB; };

    float c[4][8][4];
#pragma unroll
    for (int mi = 0; mi < 4; mi++)
#pragma unroll
        for (int ni = 0; ni < 8; ni++)
#pragma unroll
            for (int j = 0; j < 4; j++) c[mi][ni][j] = 0.0f;

    auto prefetch = [&](int kt, int s) {
        const __half* Ab = A + (size_t)m0 * DIM + kt * GBK;
        const __half* Bb = W + (size_t)n0 * DIM + kt * GBK;
        unsigned sa = stA(s), sb = stB(s);
#pragma unroll
        for (int t = tid; t < 1024; t += 128) {
            int r = t >> 3, u = t & 7;
            cpa16s(sa + (r * GST + u * 8) * 2, Ab + (size_t)r * DIM + u * 8);
        }
#pragma unroll
        for (int t = tid; t < 1024; t += 128) {
            int r = t >> 3, u = t & 7;
            cpa16s(sb + (r * GST + u * 8) * 2, Bb + (size_t)r * DIM + u * 8);
        }
    };

    prefetch(0, 0); CP_COMMIT();
    prefetch(1, 1); CP_COMMIT();

    // ldmatrix lane addressing
    const int la_r = lane & 15, la_k = (lane >> 4) * 8;              // A frags
    const int lb_n = (lane >> 4) * 8 + (lane & 7);                   // B frags
    const int lb_k = ((lane >> 3) & 1) * 8;

    for (int kt = 0; kt < NKCH; kt++) {
        const int s = kt % GSTG;
        if (kt == NKCH - 1) { CP_WAIT(0); } else { CP_WAIT(1); }
        __syncthreads();
        if (kt + 2 < NKCH) {
            prefetch(kt + 2, (kt + 2) % GSTG);
            CP_COMMIT();
        }
        const unsigned sa = stA(s), sb = stB(s);
#pragma unroll
        for (int kk = 0; kk < 4; kk++) {
            // Batch ALL fragment loads first: 8 back-to-back LDSM.x4.
            // Results complete in order; MMAs consume them while later
            // LDSMs are still in flight (hides the ~29cyc smem latency).
            unsigned am[4][4];
            unsigned bm[4][4];
#pragma unroll
            for (int mi = 0; mi < 4; mi++)
                ldsm4(am[mi][0], am[mi][1], am[mi][2], am[mi][3],
                      sa + ((wm * 64 + mi * 16 + la_r) * GST + kk * 16 + la_k) * 2);
#pragma unroll
            for (int nt = 0; nt < 4; nt++)
                ldsm4(bm[nt][0], bm[nt][1], bm[nt][2], bm[nt][3],
                      sb + ((wn * 64 + nt * 16 + lb_n) * GST + kk * 16 + lb_k) * 2);
#pragma unroll
            for (int nt = 0; nt < 4; nt++)
#pragma unroll
                for (int mi = 0; mi < 4; mi++) {
                    mma16816(c[mi][2 * nt],     am[mi], bm[nt][0], bm[nt][1]);
                    mma16816(c[mi][2 * nt + 1], am[mi], bm[nt][2], bm[nt][3]);
                }
        }
    }

    // ---- register-direct epilogue ----
    const int qd = lane >> 2, ql = lane & 3;
    const int nbase = n0 + wn * 64;
    if (mode == 1) {
#pragma unroll
        for (int mi = 0; mi < 4; mi++) {
            int mr0 = m0 + wm * 64 + mi * 16 + qd;
            float* d0 = outf + (size_t)mr0 * DIM + nbase;
            float* d1 = d0 + 8 * DIM;
#pragma unroll
            for (int ni = 0; ni < 8; ni++) {
                int col = ni * 8 + ql * 2;
                float2 bv = *reinterpret_cast<const float2*>(bias + nbase + col);
                float2 lo = make_float2(c[mi][ni][0] + bv.x, c[mi][ni][1] + bv.y);
                float2 hi = make_float2(c[mi][ni][2] + bv.x, c[mi][ni][3] + bv.y);
                *reinterpret_cast<float2*>(d0 + col) = lo;
                *reinterpret_cast<float2*>(d1 + col) = hi;
            }
        }
    } else {
        const int which = nbase / DIM;
        const int rem = nbase - which * DIM;
        const int h = rem >> 6;                    // 64-aligned head
        __half* dstB = (which == 0) ? g_Q : (which == 1) ? g_K : g_V;
        const float scl = (which == 0) ? 0.125f : 1.0f;
#pragma unroll
        for (int mi = 0; mi < 4; mi++) {
            int mr0 = m0 + wm * 64 + mi * 16 + qd;
            int mr1 = mr0 + 8;
            int b0r = mr0 / NN, t0 = mr0 - b0r * NN;
            int b1r = mr1 / NN, t1 = mr1 - b1r * NN;
            __half* p0 = dstB + ((size_t)(b0r * HH + h) * NN + t0) * DH;
            __half* p1 = dstB + ((size_t)(b1r * HH + h) * NN + t1) * DH;
#pragma unroll
            for (int ni = 0; ni < 8; ni++) {
                int d = ni * 8 + ql * 2;
                *reinterpret_cast<__half2*>(p0 + d) =
                    __floats2half2_rn(c[mi][ni][0] * scl, c[mi][ni][1] * scl);
                *reinterpret_cast<__half2*>(p1 + d) =
                    __floats2half2_rn(c[mi][ni][2] * scl, c[mi][ni][3] * scl);
            }
        }
    }
}

// ---------------- FA2-style attention (unchanged) ----------------------------
#define SMEM_ATTN (2 * NP * 72 * 2)

__global__ __launch_bounds__(256)
void attn_kernel() {
    extern __shared__ __align__(16) char sm[];
    __half* Ksm = reinterpret_cast<__half*>(sm);
    __half* Vsm = reinterpret_cast<__half*>(sm + NP * 72 * 2);

    const int bh = blockIdx.x;
    const int b = bh / HH, h = bh - b * HH;
    const __half* Kg = g_K + (size_t)bh * NN * DH;
    const __half* Vg = g_V + (size_t)bh * NN * DH;
    const __half* Qg = g_Q + (size_t)bh * NN * DH;
    const float* biasH = g_bias + (size_t)h * NPR * NP;
    const int tid = threadIdx.x, lane = tid & 31, wid = tid >> 5;

    for (int idx = tid; idx < NP * 8; idx += 256) {
        int r = idx >> 3, c = idx & 7;
        uint4 z = make_uint4(0, 0, 0, 0);
        uint4 kv = (r < NN) ? *reinterpret_cast<const uint4*>(&Kg[r * DH + c * 8]) : z;
        uint4 vv = (r < NN) ? *reinterpret_cast<const uint4*>(&Vg[r * DH + c * 8]) : z;
        *reinterpret_cast<uint4*>(&Ksm[r * 72 + c * 8]) = kv;
        *reinterpret_cast<uint4*>(&Vsm[r * 72 + c * 8]) = vv;
    }
    __syncthreads();

    const int qd = lane >> 2;
    const int ql = lane & 3;

    for (int strip = wid; strip < 13; strip += 8) {
        const int r0 = strip * 16;
        const int row0 = r0 + qd;
        const int row1 = row0 + 8;

        unsigned a[4][4];
        {
            const __half2* Qa = reinterpret_cast<const __half2*>(
                Qg + (size_t)min(row0, NN - 1) * DH);
            const __half2* Qb = reinterpret_cast<const __half2*>(
                Qg + (size_t)min(row1, NN - 1) * DH);
#pragma unroll
            for (int kk = 0; kk < 4; kk++) {
                a[kk][0] = reinterpret_cast<const unsigned*>(Qa)[kk * 8 + ql];
                a[kk][1] = reinterpret_cast<const unsigned*>(Qb)[kk * 8 + ql];
                a[kk][2] = reinterpret_cast<const unsigned*>(Qa)[kk * 8 + 4 + ql];
                a[kk][3] = reinterpret_cast<const unsigned*>(Qb)[kk * 8 + 4 + ql];
            }
        }

        float c[25][4];
#pragma unroll
        for (int nb = 0; nb < 25; nb++) {
            float2 b0 = *reinterpret_cast<const float2*>(
                biasH + (size_t)row0 * NP + nb * 8 + ql * 2);
            float2 b1 = *reinterpret_cast<const float2*>(
                biasH + (size_t)row1 * NP + nb * 8 + ql * 2);
            c[nb][0] = b0.x; c[nb][1] = b0.y; c[nb][2] = b1.x; c[nb][3] = b1.y;
        }

        const int ln = (lane >> 4) * 8 + (lane & 7);
        const int lk = ((lane >> 3) & 1) * 8;
#pragma unroll
        for (int np = 0; np < 13; np++) {
#pragma unroll
            for (int kk = 0; kk < 4; kk++) {
                unsigned b0, b1, b2, b3;
                ldsm4p(b0, b1, b2, b3, Ksm + (np * 16 + ln) * 72 + kk * 16 + lk);
                mma16816(c[2 * np], a[kk], b0, b1);
                if (np < 12) mma16816(c[2 * np + 1], a[kk], b2, b3);
            }
        }

        {
            int c0 = 192 + ql * 2;
            if (c0 >= NN)     { c[24][0] = -1e30f; c[24][2] = -1e30f; }
            if (c0 + 1 >= NN) { c[24][1] = -1e30f; c[24][3] = -1e30f; }
        }

        float m0 = -1e30f, m1 = -1e30f;
#pragma unroll
        for (int nb = 0; nb < 25; nb++) {
            m0 = fmaxf(m0, fmaxf(c[nb][0], c[nb][1]));
            m1 = fmaxf(m1, fmaxf(c[nb][2], c[nb][3]));
        }
        m0 = fmaxf(m0, __shfl_xor_sync(~0u, m0, 1));
        m0 = fmaxf(m0, __shfl_xor_sync(~0u, m0, 2));
        m1 = fmaxf(m1, __shfl_xor_sync(~0u, m1, 1));
        m1 = fmaxf(m1, __shfl_xor_sync(~0u, m1, 2));

        float s0 = 0.0f, s1 = 0.0f;
        unsigned p[25];
#pragma unroll
        for (int nb = 0; nb < 25; nb++) {
            float e0 = __expf(c[nb][0] - m0);
            float e1 = __expf(c[nb][1] - m0);
            float e2 = __expf(c[nb][2] - m1);
            float e3 = __expf(c[nb][3] - m1);
            s0 += e0 + e1;
            s1 += e2 + e3;
            __half2 lo = __floats2half2_rn(e0, e1);
            __half2 hi = __floats2half2_rn(e2, e3);
            p[nb] = h2_as_u(lo);
            c[nb][2] = __uint_as_float(h2_as_u(hi));
        }
        s0 += __shfl_xor_sync(~0u, s0, 1);
        s0 += __shfl_xor_sync(~0u, s0, 2);
        s1 += __shfl_xor_sync(~0u, s1, 1);
        s1 += __shfl_xor_sync(~0u, s1, 2);
        float rinv0 = 1.0f / s0, rinv1 = 1.0f / s1;

        float o[8][4];
#pragma unroll
        for (int d = 0; d < 8; d++)
#pragma unroll
            for (int j = 0; j < 4; j++) o[d][j] = 0.0f;

        const int lkv = ((lane >> 3) & 1) * 8 + (lane & 7);
        const int ldv = (lane >> 4) * 8;
#pragma unroll
        for (int kc = 0; kc < 13; kc++) {
            unsigned pa[4];
            pa[0] = p[2 * kc];
            pa[1] = __float_as_uint(c[2 * kc][2]);
            if (kc < 12) {
                pa[2] = p[2 * kc + 1];
                pa[3] = __float_as_uint(c[2 * kc + 1][2]);
            } else {
                pa[2] = 0; pa[3] = 0;
            }
#pragma unroll
            for (int dp = 0; dp < 4; dp++) {
                unsigned b0, b1, b2, b3;
                ldsm4t(b0, b1, b2, b3, Vsm + (kc * 16 + lkv) * 72 + dp * 16 + ldv);
                mma16816(o[2 * dp], pa, b0, b1);
                mma16816(o[2 * dp + 1], pa, b2, b3);
            }
        }

        if (row0 < NN) {
            __half2* op = reinterpret_cast<__half2*>(
                g_AO + (size_t)(b * NN + row0) * DIM + h * DH);
#pragma unroll
            for (int d = 0; d < 8; d++)
                op[d * 4 + ql] = __floats2half2_rn(o[d][0] * rinv0, o[d][1] * rinv0);
        }
        if (row1 < NN) {
            __half2* op = reinterpret_cast<__half2*>(
                g_AO + (size_t)(b * NN + row1) * DIM + h * DH);
#pragma unroll
            for (int d = 0; d < 8; d++)
                op[d * 4 + ql] = __floats2half2_rn(o[d][2] * rinv1, o[d][3] * rinv1);
        }
    }
}

// ---------------- launch ----------------
extern "C" void kernel_launch(void* const* d_in, const int* in_sizes, int n_in,
                              void* d_out, int out_size) {
    const float* x     = (const float*)d_in[0];
    const float* qkvw  = (const float*)d_in[1];
    const float* projw = (const float*)d_in[2];
    const float* projb = (const float*)d_in[3];
    const float* btab  = (const float*)d_in[4];
    const int*   ridx  = (const int*)d_in[5];
    float* out = (float*)d_out;

    cudaFuncSetAttribute(attn_kernel, cudaFuncAttributeMaxDynamicSharedMemorySize,
                         SMEM_ATTN);
    cudaFuncSetAttribute(gemm_kernel, cudaFuncAttributeMaxDynamicSharedMemorySize,
                         SMEM_G);

    f2h_x<<<(NX2 + 255) / 256, 256>>>(x);                            // 0
    f2h_w<<<(NW12 + NW22 + 255) / 256, 256>>>(qkvw, projw);          // 1

    const int nb = HH * NPR * NP;
    bias_kernel<<<(nb + 255) / 256, 256>>>(btab, ridx);              // 2

    // QKV: M=25216 (197 tiles), N=2304 (18 tiles)                    // 3 (profiled)
    gemm_kernel<<<dim3(18, 197), 128, SMEM_G>>>(0, nullptr, nullptr);

    attn_kernel<<<BB * HH, 256, SMEM_ATTN>>>();                      // 4

    // proj: N=768 (6 tiles)                                          // 5
    gemm_kernel<<<dim3(6, 197), 128, SMEM_G>>>(1, projb, out);
}